// round 10
// baseline (speedup 1.0000x reference)
#include <cuda_runtime.h>
#include <cuda_fp16.h>
#include <math.h>
#include <stdint.h>

#define Cc 256
#define HW 16384
#define Bb 8
#define CHW (Cc*HW)
#define NTOT (Bb*HW)
#define TOTAL (Bb*CHW)
#define PROB_OFF TOTAL
#define NS 50

#define STG 24576            // bytes per stage: A 16KB (2 parts) + B 8KB (G1) / 4KB (G2)
#define FAC_OFF (3*STG)      // 73728
#define BIAS_OFF (FAC_OFF+512)
#define SMEM_GEMM (BIAS_OFF+1024)

// ---------------- device globals ----------------
__device__ float g_h[TOTAL];                 // h pre-BN, [ch][P] fp32
__device__ __half g_B2[TOTAL];               // relu(bn(h)) fp16, pre-swizzled chunk tiles
__device__ __half g_wA[2*2*Cc*Cc];           // weights: [gemm][part][chunk][4096]
__device__ float g_sum[Cc], g_sumsq[Cc], g_bna[Cc], g_bnb[Cc];
__device__ float g_u[NTOT], g_u2[NTOT];
__device__ unsigned int g_minb, g_maxb;

union H8 { __half h[8]; uint4 v; };

__device__ __forceinline__ uint32_t s2u(const void* p) {
    uint32_t a;
    asm("{ .reg .u64 t; cvta.to.shared.u64 t, %1; cvt.u32.u64 %0, t; }" : "=r"(a) : "l"(p));
    return a;
}
__device__ __forceinline__ void cpa16(uint32_t dst, const void* src) {
    asm volatile("cp.async.cg.shared.global [%0], [%1], 16;" :: "r"(dst), "l"(src));
}
__device__ __forceinline__ void ldmx4(uint32_t& a0, uint32_t& a1, uint32_t& a2, uint32_t& a3, uint32_t ad) {
    asm volatile("ldmatrix.sync.aligned.m8n8.x4.shared.b16 {%0,%1,%2,%3}, [%4];"
                 : "=r"(a0), "=r"(a1), "=r"(a2), "=r"(a3) : "r"(ad));
}
__device__ __forceinline__ void ldmx2(uint32_t& b0, uint32_t& b1, uint32_t ad) {
    asm volatile("ldmatrix.sync.aligned.m8n8.x2.shared.b16 {%0,%1}, [%2];"
                 : "=r"(b0), "=r"(b1) : "r"(ad));
}
__device__ __forceinline__ void mma16816(float* d, const uint32_t* a, uint32_t b0, uint32_t b1) {
    asm volatile("mma.sync.aligned.m16n8k16.row.col.f32.f16.f16.f32 "
                 "{%0,%1,%2,%3}, {%4,%5,%6,%7}, {%8,%9}, {%0,%1,%2,%3};"
                 : "+f"(d[0]), "+f"(d[1]), "+f"(d[2]), "+f"(d[3])
                 : "r"(a[0]), "r"(a[1]), "r"(a[2]), "r"(a[3]), "r"(b0), "r"(b1));
}

// ---------------- weight prep (+ per-call init, fused) ----------------
__global__ void k_prep_w(const float* __restrict__ Wp, const float* __restrict__ Wc) {
    int t = threadIdx.x;
    if (blockIdx.x == 0) {
        g_sum[t] = 0.f; g_sumsq[t] = 0.f;
        if (t == 0) { g_minb = 0xFFFFFFFFu; g_maxb = 0u; }
    }
    int idx = blockIdx.x * blockDim.x + t;             // 0..131071
    int g = idx >> 16, ch = (idx >> 8) & 255, k = idx & 255;
    float w = (g ? Wc : Wp)[ch * Cc + k];
    __half H = __float2half_rn(w);
    __half L = __float2half_rn(w - __half2float(H));
    int kc = k >> 4, kk = k & 15;
    int unit = ((kk >> 3) ^ (ch >> 2)) & 1;
    int elem = (ch * 32 + unit * 16 + (kk & 7) * 2) >> 1;
    size_t base = (size_t)((g * 2) * 16 + kc) * 4096 + elem;
    g_wA[base]         = H;
    g_wA[base + 65536] = L;     // part stride = 16 chunks * 4096
}

// ---------------- mma.sync GEMM: tile 256ch x 128pix, K=256 in 16 chunks, 3-stage ----------------
// G=1: B = x fp32 (2-way fp16 split, 3 terms), epilogue -> g_h + BN stats
// G=2: B = g_B2 fp16 via cp.async (2 terms: AhBh+AlBh), epilogue -> out with bias + (1-u)*mask
template<int G>
__global__ __launch_bounds__(256, 1)
void k_gemm(const float* __restrict__ x, float* __restrict__ out,
            const float* __restrict__ bconv, const float* __restrict__ randu) {
    extern __shared__ __align__(16) char sm[];
    const uint32_t sb = s2u(sm);
    const int t = threadIdx.x, wid = t >> 5, lane = t & 31;
    const int P0 = blockIdx.x * 128;

    const int ch0 = (wid >> 1) * 64;
    const int pix0w = (wid & 1) * 64;
    const int aRow = lane & 15, aUnit = lane >> 4;
    const int l15 = lane & 15;
    const int bRowOff = l15 & 7, bUnit = (l15 >> 3) & 1;
    const int px = t & 127, kg = t >> 7;       // G1 B loader: pixel + k-half

    float* s_fac  = (float*)(sm + FAC_OFF);
    float* s_bias = (float*)(sm + BIAS_OFF);
    if (G == 2) {
        if (t < 128) {
            float mn = __uint_as_float(g_minb), mx = __uint_as_float(g_maxb);
            float un = (g_u2[P0 + t] - mn) / (mx - mn);
            s_fac[t] = (1.f - un) * ((un < randu[P0 + t]) ? 1.f : 0.f);
        }
        s_bias[t] = bconv[t];
    }

    float d[4][8][4];
#pragma unroll
    for (int i = 0; i < 4; i++)
#pragma unroll
        for (int j = 0; j < 8; j++)
#pragma unroll
            for (int e = 0; e < 4; e++) d[i][j][e] = 0.f;

    float bf2[2][8];
    const float* xs = x + (size_t)(P0 >> 14) * CHW + (P0 & 16383) + px;

#define ISSUE_A(cc, so) do { \
    _Pragma("unroll") \
    for (int i = 0; i < 4; i++) { \
        int u = t + i * 256; \
        int p = u >> 9, w = u & 511; \
        const char* src = (const char*)g_wA + (size_t)(((G - 1) * 2 + p) * 16 + (cc)) * 8192 + w * 16; \
        cpa16(sb + (so) + p * 8192 + w * 16, src); \
    } \
    if (G == 2) { \
        const char* srcb = (const char*)g_B2 + ((size_t)(blockIdx.x * 16 + (cc)) * 4096) + t * 16; \
        cpa16(sb + (so) + 16384 + t * 16, srcb); \
    } \
    asm volatile("cp.async.commit_group;"); \
} while (0)

#define LOAD_B(cc, rs) do { \
    if (G == 1) { \
        _Pragma("unroll") \
        for (int e = 0; e < 8; e++) bf2[rs][e] = xs[(size_t)((cc) * 16 + kg * 8 + e) * HW]; \
    } \
} while (0)

#define STORE_B(so, rs) do { \
    if (G == 1) { \
        H8 u0, u1; \
        _Pragma("unroll") \
        for (int e = 0; e < 8; e++) { \
            u0.h[e] = __float2half_rn(bf2[rs][e]); \
            u1.h[e] = __float2half_rn(bf2[rs][e] - __half2float(u0.h[e])); \
        } \
        int u2 = (kg ^ (px >> 2)) & 1; \
        char* dst = sm + (so) + 16384 + px * 32 + u2 * 16; \
        *(uint4*)(dst) = u0.v; \
        *(uint4*)(dst + 4096) = u1.v; \
    } \
} while (0)

    // prologue: stage chunks 0 and 1
    LOAD_B(0, 0);
    ISSUE_A(0, 0);
    STORE_B(0, 0);
    LOAD_B(1, 1);
    ISSUE_A(1, STG);
    asm volatile("cp.async.wait_group 1;");   // chunk 0's group complete
    __syncthreads();

    for (int c = 0; c < 16; c++) {
        const uint32_t so_cur = (c % 3) * STG;
        const uint32_t so_nx1 = ((c + 1) % 3) * STG;
        const uint32_t so_nx2 = ((c + 2) % 3) * STG;
        if (c + 2 < 16) {
            ISSUE_A(c + 2, so_nx2);
            LOAD_B(c + 2, c & 1);
        }
        if (c + 1 < 16) STORE_B(so_nx1, (c + 1) & 1);
        // ---- MMA on current stage ----
        {
            uint32_t Ast = sb + so_cur;
            uint32_t Bst = Ast + 16384;
            constexpr int NPB = (G == 1) ? 2 : 1;
            uint32_t Bf[NPB][8][2];
#pragma unroll
            for (int p = 0; p < NPB; p++)
#pragma unroll
                for (int nt = 0; nt < 8; nt++) {
                    int row = pix0w + nt * 8 + bRowOff;
                    uint32_t ad = Bst + p * 4096 + row * 32 + (((bUnit ^ (row >> 2)) & 1) << 4);
                    ldmx2(Bf[p][nt][0], Bf[p][nt][1], ad);
                }
#pragma unroll
            for (int mt = 0; mt < 4; mt++) {
#pragma unroll
                for (int pa = 0; pa < 2; pa++) {
                    int row = ch0 + mt * 16 + aRow;
                    uint32_t ad = Ast + pa * 8192 + row * 32 + (((aUnit ^ (row >> 2)) & 1) << 4);
                    uint32_t a[4];
                    ldmx4(a[0], a[1], a[2], a[3], ad);
                    const int nb = (G == 1) ? (2 - pa) : 1;   // G1: AhBh,AhBl,AlBh  G2: AhBh,AlBh
#pragma unroll
                    for (int pb = 0; pb < NPB; pb++) {
                        if (pb >= nb) break;
#pragma unroll
                        for (int nt = 0; nt < 8; nt++)
                            mma16816(d[mt][nt], a, Bf[pb][nt][0], Bf[pb][nt][1]);
                    }
                }
            }
        }
        if (c + 2 < 16)      asm volatile("cp.async.wait_group 1;");  // chunk c+1 ready
        else if (c + 1 < 16) asm volatile("cp.async.wait_group 0;");
        __syncthreads();
    }

    // ---- epilogue ----
    const int rq = lane >> 2, q = lane & 3;
    if (G == 1) {
        float* s_sum = (float*)sm;
        float* s_sq = s_sum + 256;
        s_sum[t] = 0.f; s_sq[t] = 0.f;
        __syncthreads();
#pragma unroll
        for (int mt = 0; mt < 4; mt++) {
            int c_0 = ch0 + mt * 16 + rq, c_1 = c_0 + 8;
            float s0 = 0.f, q0 = 0.f, s1 = 0.f, q1 = 0.f;
#pragma unroll
            for (int nt = 0; nt < 8; nt++) {
                float v0 = d[mt][nt][0], v1 = d[mt][nt][1];
                float v2 = d[mt][nt][2], v3 = d[mt][nt][3];
                size_t PP = (size_t)P0 + pix0w + nt * 8 + q * 2;
                *(float2*)&g_h[(size_t)c_0 * NTOT + PP] = make_float2(v0, v1);
                *(float2*)&g_h[(size_t)c_1 * NTOT + PP] = make_float2(v2, v3);
                s0 += v0 + v1; q0 += v0 * v0 + v1 * v1;
                s1 += v2 + v3; q1 += v2 * v2 + v3 * v3;
            }
#pragma unroll
            for (int o = 1; o <= 2; o <<= 1) {
                s0 += __shfl_xor_sync(0xFFFFFFFFu, s0, o);
                q0 += __shfl_xor_sync(0xFFFFFFFFu, q0, o);
                s1 += __shfl_xor_sync(0xFFFFFFFFu, s1, o);
                q1 += __shfl_xor_sync(0xFFFFFFFFu, q1, o);
            }
            if (q == 0) {
                atomicAdd(&s_sum[c_0], s0); atomicAdd(&s_sq[c_0], q0);
                atomicAdd(&s_sum[c_1], s1); atomicAdd(&s_sq[c_1], q1);
            }
        }
        __syncthreads();
        atomicAdd(&g_sum[t], s_sum[t]);
        atomicAdd(&g_sumsq[t], s_sq[t]);
    } else {
        const size_t obase = (size_t)(P0 >> 14) * CHW + (P0 & 16383);
#pragma unroll
        for (int mt = 0; mt < 4; mt++) {
            int c_0 = ch0 + mt * 16 + rq, c_1 = c_0 + 8;
            float b0 = s_bias[c_0], b1 = s_bias[c_1];
#pragma unroll
            for (int nt = 0; nt < 8; nt++) {
                int pixL = pix0w + nt * 8 + q * 2;
                float f0 = s_fac[pixL], f1 = s_fac[pixL + 1];
                *(float2*)&out[obase + (size_t)c_0 * HW + pixL] =
                    make_float2((d[mt][nt][0] + b0) * f0, (d[mt][nt][1] + b0) * f1);
                *(float2*)&out[obase + (size_t)c_1 * HW + pixL] =
                    make_float2((d[mt][nt][2] + b1) * f0, (d[mt][nt][3] + b1) * f1);
            }
        }
    }
#undef ISSUE_A
#undef LOAD_B
#undef STORE_B
}

// ---------------- BN finalize ----------------
__global__ void k_bnfin(const float* __restrict__ gamma, const float* __restrict__ beta) {
    int c = threadIdx.x;
    float n = (float)NTOT;
    float mu = g_sum[c] / n;
    float var = fmaxf(g_sumsq[c] / n - mu * mu, 0.f);
    float a = gamma[c] * rsqrtf(var + 1e-5f);
    g_bna[c] = a; g_bnb[c] = beta[c] - mu * a;
}

// ---------------- fused: BN+ReLU -> g_B2 (fp16 tiled), mean/logvar GEMV, prob_x, u ----------------
__global__ void k_fuse(const float* __restrict__ Wm, const float* __restrict__ Ws,
                       const float* __restrict__ eps1, const float* __restrict__ eps50,
                       float* __restrict__ out) {
    __shared__ float s_a[Cc], s_b[Cc], s_wm[Cc], s_ws[Cc];
    int t = threadIdx.x;
    s_a[t] = g_bna[t]; s_b[t] = g_bnb[t]; s_wm[t] = Wm[t]; s_ws[t] = Ws[t];
    __syncthreads();
    int P = blockIdx.x * 256 + t;
    int tile = P >> 7, px = P & 127;
    float m = 0.f, lv = 0.f;
#pragma unroll 4
    for (int cc = 0; cc < 16; cc++) {
#pragma unroll
        for (int kg = 0; kg < 2; kg++) {
            H8 u0;
#pragma unroll
            for (int e = 0; e < 8; e++) {
                int ch = cc * 16 + kg * 8 + e;
                float v = g_h[(size_t)ch * NTOT + P];
                float r = fmaxf(fmaf(s_a[ch], v, s_b[ch]), 0.f);
                m = fmaf(s_wm[ch], r, m);
                lv = fmaf(s_ws[ch], r, lv);
                u0.h[e] = __float2half_rn(r);
            }
            int u2 = (kg ^ (px >> 2)) & 1;
            *(uint4*)(g_B2 + (size_t)(tile * 16 + cc) * 2048 + px * 16 + u2 * 8) = u0.v;
        }
    }
    float stdv = __expf(0.5f * lv);
    out[PROB_OFF + P] = fmaf(eps1[P], stdv, m);
    int b = P >> 14, hw = P & (HW - 1);
    const float* e = eps50 + (size_t)b * NS * HW + hw;
    float v[NS], s = 0.f;
#pragma unroll
    for (int i = 0; i < NS; i++) {
        float tt = fmaf(e[(size_t)i * HW], stdv, m);
        float pv = __fdividef(1.f, 1.f + __expf(-tt));
        v[i] = pv; s += pv;
    }
    float mm = s * (1.f / NS), ss = 0.f;
#pragma unroll
    for (int i = 0; i < NS; i++) { float dd = v[i] - mm; ss = fmaf(dd, dd, ss); }
    g_u[P] = ss * (1.f / (NS - 1));
}

// ---------------- 3x 7x7 box filter, banded (64 blocks), + global min/max ----------------
#define BAND 16
#define HALO 9
#define LROWS (BAND + 2*HALO)   // 34
__global__ void k_box() {
    __shared__ float s0[LROWS][128], s1[LROWS][128];
    __shared__ unsigned int smn, smx;
    const int band = blockIdx.x, b = blockIdx.y;
    const int r0 = band * BAND - HALO;     // global row of ly=0
    const int tid = threadIdx.x;
    if (tid == 0) { smn = 0xFFFFFFFFu; smx = 0u; }
    const float* up = g_u + (size_t)b * HW;
    for (int i = tid; i < LROWS * 128; i += 256) {
        int ly = i >> 7, xx = i & 127;
        int gy = r0 + ly;
        s0[ly][xx] = (gy >= 0 && gy < 128) ? up[(gy << 7) + xx] : 0.f;
    }
    __syncthreads();
    int lo = 0, hi = LROWS;
    for (int it = 0; it < 3; it++) {
        for (int i = tid; i < LROWS * 128; i += 256) {
            int ly = i >> 7, xx = i & 127;
            if (ly >= lo && ly < hi) {
                int x0 = xx - 3 < 0 ? 0 : xx - 3;
                int x1 = xx + 3 > 127 ? 127 : xx + 3;
                float s = 0.f;
                for (int x2 = x0; x2 <= x1; x2++) s += s0[ly][x2];
                s1[ly][xx] = s;
            }
        }
        __syncthreads();
        lo += 3; hi -= 3;
        for (int i = tid; i < LROWS * 128; i += 256) {
            int ly = i >> 7, xx = i & 127;
            if (ly >= lo && ly < hi) {
                int gy = r0 + ly;
                float s = 0.f;
#pragma unroll
                for (int yy = -3; yy <= 3; yy++) s += s1[ly + yy][xx];
                s0[ly][xx] = (gy >= 0 && gy < 128) ? s : 0.f;   // per-iter zero pad
            }
        }
        __syncthreads();
    }
    float lmn = 3.4e38f, lmx = -3.4e38f;
    float* op = g_u2 + (size_t)b * HW + band * BAND * 128;
    for (int i = tid; i < BAND * 128; i += 256) {
        int ly = HALO + (i >> 7), xx = i & 127;
        float v = s0[ly][xx];
        op[i] = v;
        lmn = fminf(lmn, v); lmx = fmaxf(lmx, v);
    }
    atomicMin(&smn, __float_as_uint(lmn));
    atomicMax(&smx, __float_as_uint(lmx));
    __syncthreads();
    if (tid == 0) { atomicMin(&g_minb, smn); atomicMax(&g_maxb, smx); }
}

// ---------------- launch ----------------
extern "C" void kernel_launch(void* const* d_in, const int* in_sizes, int n_in,
                              void* d_out, int out_size) {
    const float* x     = (const float*)d_in[0];
    const float* Wproj = (const float*)d_in[1];
    const float* gamma = (const float*)d_in[2];
    const float* beta  = (const float*)d_in[3];
    const float* Wconv = (const float*)d_in[4];
    const float* bconv = (const float*)d_in[5];
    const float* Wmean = (const float*)d_in[6];
    const float* Wstd  = (const float*)d_in[7];
    const float* eps1  = (const float*)d_in[8];
    const float* eps50 = (const float*)d_in[9];
    const float* randu = (const float*)d_in[10];
    float* out = (float*)d_out;

    cudaFuncSetAttribute(k_gemm<1>, cudaFuncAttributeMaxDynamicSharedMemorySize, SMEM_GEMM);
    cudaFuncSetAttribute(k_gemm<2>, cudaFuncAttributeMaxDynamicSharedMemorySize, SMEM_GEMM);

    k_prep_w<<<512, 256>>>(Wproj, Wconv);
    k_gemm<1><<<NTOT / 128, 256, SMEM_GEMM>>>(x, nullptr, nullptr, nullptr);
    k_bnfin<<<1, 256>>>(gamma, beta);
    k_fuse<<<NTOT / 256, 256>>>(Wmean, Wstd, eps1, eps50, out);
    k_box<<<dim3(Bb, Bb), 256>>>();
    k_gemm<2><<<NTOT / 128, 256, SMEM_GEMM>>>(nullptr, out, bconv, randu);
}

// round 11
// speedup vs baseline: 1.1683x; 1.1683x over previous
#include <cuda_runtime.h>
#include <cuda_fp16.h>
#include <math.h>
#include <stdint.h>

#define Cc 256
#define HW 16384
#define Bb 8
#define CHW (Cc*HW)
#define NTOT (Bb*HW)
#define TOTAL (Bb*CHW)
#define PROB_OFF TOTAL
#define NS 50

#define STG 24576            // bytes per stage (G1 uses all; G2 uses 12KB of it)
#define FAC_OFF (2*STG)      // 49152
#define BIAS_OFF (FAC_OFF+512)
#define SMEM_GEMM (BIAS_OFF+1024)

// ---------------- device globals ----------------
__device__ float g_h[TOTAL];                 // h pre-BN, [ch][P] fp32
__device__ __half g_B2[TOTAL];               // relu(bn(h)) fp16, pre-swizzled chunk tiles
__device__ __half g_wA[2*2*Cc*Cc];           // weights: [gemm][part][chunk][4096]
__device__ float g_sum[Cc], g_sumsq[Cc], g_bna[Cc], g_bnb[Cc];
__device__ float g_u[NTOT], g_u2[NTOT];
__device__ unsigned int g_minb, g_maxb;

union H8 { __half h[8]; uint4 v; };

__device__ __forceinline__ uint32_t s2u(const void* p) {
    uint32_t a;
    asm("{ .reg .u64 t; cvta.to.shared.u64 t, %1; cvt.u32.u64 %0, t; }" : "=r"(a) : "l"(p));
    return a;
}
__device__ __forceinline__ void cpa16(uint32_t dst, const void* src) {
    asm volatile("cp.async.cg.shared.global [%0], [%1], 16;" :: "r"(dst), "l"(src));
}
__device__ __forceinline__ void ldmx4(uint32_t& a0, uint32_t& a1, uint32_t& a2, uint32_t& a3, uint32_t ad) {
    asm volatile("ldmatrix.sync.aligned.m8n8.x4.shared.b16 {%0,%1,%2,%3}, [%4];"
                 : "=r"(a0), "=r"(a1), "=r"(a2), "=r"(a3) : "r"(ad));
}
__device__ __forceinline__ void ldmx2(uint32_t& b0, uint32_t& b1, uint32_t ad) {
    asm volatile("ldmatrix.sync.aligned.m8n8.x2.shared.b16 {%0,%1}, [%2];"
                 : "=r"(b0), "=r"(b1) : "r"(ad));
}
__device__ __forceinline__ void mma16816(float* d, const uint32_t* a, uint32_t b0, uint32_t b1) {
    asm volatile("mma.sync.aligned.m16n8k16.row.col.f32.f16.f16.f32 "
                 "{%0,%1,%2,%3}, {%4,%5,%6,%7}, {%8,%9}, {%0,%1,%2,%3};"
                 : "+f"(d[0]), "+f"(d[1]), "+f"(d[2]), "+f"(d[3])
                 : "r"(a[0]), "r"(a[1]), "r"(a[2]), "r"(a[3]), "r"(b0), "r"(b1));
}

// ---------------- weight prep (+ per-call init, fused) ----------------
__global__ void k_prep_w(const float* __restrict__ Wp, const float* __restrict__ Wc) {
    int t = threadIdx.x;
    if (blockIdx.x == 0) {
        g_sum[t] = 0.f; g_sumsq[t] = 0.f;
        if (t == 0) { g_minb = 0xFFFFFFFFu; g_maxb = 0u; }
    }
    int idx = blockIdx.x * blockDim.x + t;             // 0..131071
    int g = idx >> 16, ch = (idx >> 8) & 255, k = idx & 255;
    float w = (g ? Wc : Wp)[ch * Cc + k];
    __half H = __float2half_rn(w);
    __half L = __float2half_rn(w - __half2float(H));
    int kc = k >> 4, kk = k & 15;
    int unit = ((kk >> 3) ^ (ch >> 2)) & 1;
    int elem = (ch * 32 + unit * 16 + (kk & 7) * 2) >> 1;
    size_t base = (size_t)((g * 2) * 16 + kc) * 4096 + elem;
    g_wA[base]         = H;
    g_wA[base + 65536] = L;     // part stride = 16 chunks * 4096
}

// ---------------- mma.sync GEMM, K=256 in 16 chunks, 2-stage ----------------
// G=1: tile 256ch x 128px, occ 1. B = x fp32 (2-way fp16 split, 3 terms) -> g_h + BN stats
// G=2: tile 128ch x 128px, occ 2 (M split across CTA pairs). B = g_B2 via cp.async
//      (2 terms: AhBh+AlBh) -> out with bias + (1-u)*mask
template<int G>
__global__ __launch_bounds__(256, G)
void k_gemm(const float* __restrict__ x, float* __restrict__ out,
            const float* __restrict__ bconv, const float* __restrict__ randu) {
    extern __shared__ __align__(16) char sm[];
    const uint32_t sb = s2u(sm);
    const int t = threadIdx.x, wid = t >> 5, lane = t & 31;
    const int tileIdx = (G == 1) ? blockIdx.x : (blockIdx.x >> 1);
    const int mhalf   = (G == 1) ? 0 : (blockIdx.x & 1);
    const int P0 = tileIdx * 128;
    constexpr int MT  = (G == 1) ? 4 : 2;       // 16-ch M-tiles per warp-group
    constexpr int APS = (G == 1) ? 8192 : 4096; // A part stride in stage
    constexpr int BOF = (G == 1) ? 16384 : 8192;// B offset in stage

    const int ch0 = mhalf * 128 + (wid >> 1) * (MT * 16);
    const int ch0l = (wid >> 1) * (MT * 16);    // local A-tile row base
    const int pix0w = (wid & 1) * 64;
    const int aRow = lane & 15, aUnit = lane >> 4;
    const int l15 = lane & 15;
    const int bRowOff = l15 & 7, bUnit = (l15 >> 3) & 1;
    const int px = t & 127, kg = t >> 7;       // G1 B loader: pixel + k-half

    float* s_fac  = (float*)(sm + FAC_OFF);
    float* s_bias = (float*)(sm + BIAS_OFF);
    if (G == 2) {
        if (t < 128) {
            float mn = __uint_as_float(g_minb), mx = __uint_as_float(g_maxb);
            float un = (g_u2[P0 + t] - mn) / (mx - mn);
            s_fac[t] = (1.f - un) * ((un < randu[P0 + t]) ? 1.f : 0.f);
        }
        s_bias[t] = bconv[t];
    }

    float d[MT][8][4];
#pragma unroll
    for (int i = 0; i < MT; i++)
#pragma unroll
        for (int j = 0; j < 8; j++)
#pragma unroll
            for (int e = 0; e < 4; e++) d[i][j][e] = 0.f;

    float bf[8];
    const float* xs = x + (size_t)(P0 >> 14) * CHW + (P0 & 16383) + px;

#define ISSUE_A(cc, so) do { \
    if (G == 1) { \
        _Pragma("unroll") \
        for (int i = 0; i < 4; i++) { \
            int u = t + i * 256; \
            int p = u >> 9, w = u & 511; \
            const char* src = (const char*)g_wA + (size_t)(p * 16 + (cc)) * 8192 + w * 16; \
            cpa16(sb + (so) + p * 8192 + w * 16, src); \
        } \
    } else { \
        _Pragma("unroll") \
        for (int i = 0; i < 2; i++) { \
            int u = t + i * 256; \
            int p = u >> 8, w = u & 255; \
            const char* src = (const char*)g_wA + (size_t)((2 + p) * 16 + (cc)) * 8192 + mhalf * 4096 + w * 16; \
            cpa16(sb + (so) + p * 4096 + w * 16, src); \
        } \
        const char* srcb = (const char*)g_B2 + ((size_t)(tileIdx * 16 + (cc)) * 4096) + t * 16; \
        cpa16(sb + (so) + BOF + t * 16, srcb); \
    } \
    asm volatile("cp.async.commit_group;"); \
} while (0)

#define LOAD_B(cc) do { \
    if (G == 1) { \
        _Pragma("unroll") \
        for (int e = 0; e < 8; e++) bf[e] = xs[(size_t)((cc) * 16 + kg * 8 + e) * HW]; \
    } \
} while (0)

#define STORE_B(so) do { \
    if (G == 1) { \
        H8 u0, u1; \
        _Pragma("unroll") \
        for (int e = 0; e < 8; e++) { \
            u0.h[e] = __float2half_rn(bf[e]); \
            u1.h[e] = __float2half_rn(bf[e] - __half2float(u0.h[e])); \
        } \
        int u2 = (kg ^ (px >> 2)) & 1; \
        char* dst = sm + (so) + BOF + px * 32 + u2 * 16; \
        *(uint4*)(dst) = u0.v; \
        *(uint4*)(dst + 4096) = u1.v; \
    } \
} while (0)

    // prologue: chunk 0
    LOAD_B(0);
    ISSUE_A(0, 0);
    STORE_B(0);
    asm volatile("cp.async.wait_group 0;");
    __syncthreads();

    for (int c = 0; c < 16; c++) {
        const uint32_t so_cur = (c & 1) * STG;
        const uint32_t so_nxt = ((c + 1) & 1) * STG;
        if (c < 15) {
            ISSUE_A(c + 1, so_nxt);
            LOAD_B(c + 1);
        }
        // ---- MMA on current stage ----
        {
            uint32_t Ast = sb + so_cur;
            uint32_t Bst = Ast + BOF;
            constexpr int NPB = (G == 1) ? 2 : 1;
            uint32_t Bf[NPB][8][2];
#pragma unroll
            for (int p = 0; p < NPB; p++)
#pragma unroll
                for (int nt = 0; nt < 8; nt++) {
                    int row = pix0w + nt * 8 + bRowOff;
                    uint32_t ad = Bst + p * 4096 + row * 32 + (((bUnit ^ (row >> 2)) & 1) << 4);
                    ldmx2(Bf[p][nt][0], Bf[p][nt][1], ad);
                }
#pragma unroll
            for (int mt = 0; mt < MT; mt++) {
#pragma unroll
                for (int pa = 0; pa < 2; pa++) {
                    int row = ch0l + mt * 16 + aRow;
                    uint32_t ad = Ast + pa * APS + row * 32 + (((aUnit ^ (row >> 2)) & 1) << 4);
                    uint32_t a[4];
                    ldmx4(a[0], a[1], a[2], a[3], ad);
                    const int nb = (G == 1) ? (2 - pa) : 1;   // G1: AhBh,AhBl,AlBh  G2: AhBh,AlBh
#pragma unroll
                    for (int pb = 0; pb < NPB; pb++) {
                        if (pb >= nb) break;
#pragma unroll
                        for (int nt = 0; nt < 8; nt++)
                            mma16816(d[mt][nt], a, Bf[pb][nt][0], Bf[pb][nt][1]);
                    }
                }
            }
        }
        if (c < 15) {
            STORE_B(so_nxt);
            asm volatile("cp.async.wait_group 0;");
        }
        __syncthreads();
    }

    // ---- epilogue ----
    const int rq = lane >> 2, q = lane & 3;
    if (G == 1) {
        float* s_sum = (float*)sm;
        float* s_sq = s_sum + 256;
        s_sum[t] = 0.f; s_sq[t] = 0.f;
        __syncthreads();
#pragma unroll
        for (int mt = 0; mt < MT; mt++) {
            int c_0 = ch0 + mt * 16 + rq, c_1 = c_0 + 8;
            float s0 = 0.f, q0 = 0.f, s1 = 0.f, q1 = 0.f;
#pragma unroll
            for (int nt = 0; nt < 8; nt++) {
                float v0 = d[mt][nt][0], v1 = d[mt][nt][1];
                float v2 = d[mt][nt][2], v3 = d[mt][nt][3];
                size_t PP = (size_t)P0 + pix0w + nt * 8 + q * 2;
                *(float2*)&g_h[(size_t)c_0 * NTOT + PP] = make_float2(v0, v1);
                *(float2*)&g_h[(size_t)c_1 * NTOT + PP] = make_float2(v2, v3);
                s0 += v0 + v1; q0 += v0 * v0 + v1 * v1;
                s1 += v2 + v3; q1 += v2 * v2 + v3 * v3;
            }
#pragma unroll
            for (int o = 1; o <= 2; o <<= 1) {
                s0 += __shfl_xor_sync(0xFFFFFFFFu, s0, o);
                q0 += __shfl_xor_sync(0xFFFFFFFFu, q0, o);
                s1 += __shfl_xor_sync(0xFFFFFFFFu, s1, o);
                q1 += __shfl_xor_sync(0xFFFFFFFFu, q1, o);
            }
            if (q == 0) {
                atomicAdd(&s_sum[c_0], s0); atomicAdd(&s_sq[c_0], q0);
                atomicAdd(&s_sum[c_1], s1); atomicAdd(&s_sq[c_1], q1);
            }
        }
        __syncthreads();
        atomicAdd(&g_sum[t], s_sum[t]);
        atomicAdd(&g_sumsq[t], s_sq[t]);
    } else {
        const size_t obase = (size_t)(P0 >> 14) * CHW + (P0 & 16383);
#pragma unroll
        for (int mt = 0; mt < MT; mt++) {
            int c_0 = ch0 + mt * 16 + rq, c_1 = c_0 + 8;
            float b0 = s_bias[c_0], b1 = s_bias[c_1];
#pragma unroll
            for (int nt = 0; nt < 8; nt++) {
                int pixL = pix0w + nt * 8 + q * 2;
                float f0 = s_fac[pixL], f1 = s_fac[pixL + 1];
                *(float2*)&out[obase + (size_t)c_0 * HW + pixL] =
                    make_float2((d[mt][nt][0] + b0) * f0, (d[mt][nt][1] + b0) * f1);
                *(float2*)&out[obase + (size_t)c_1 * HW + pixL] =
                    make_float2((d[mt][nt][2] + b1) * f0, (d[mt][nt][3] + b1) * f1);
            }
        }
    }
#undef ISSUE_A
#undef LOAD_B
#undef STORE_B
}

// ---------------- BN finalize ----------------
__global__ void k_bnfin(const float* __restrict__ gamma, const float* __restrict__ beta) {
    int c = threadIdx.x;
    float n = (float)NTOT;
    float mu = g_sum[c] / n;
    float var = fmaxf(g_sumsq[c] / n - mu * mu, 0.f);
    float a = gamma[c] * rsqrtf(var + 1e-5f);
    g_bna[c] = a; g_bnb[c] = beta[c] - mu * a;
}

// ---------------- fused: BN+ReLU -> g_B2 (fp16 tiled), mean/logvar GEMV, prob_x, u ----------------
__global__ void k_fuse(const float* __restrict__ Wm, const float* __restrict__ Ws,
                       const float* __restrict__ eps1, const float* __restrict__ eps50,
                       float* __restrict__ out) {
    __shared__ float s_a[Cc], s_b[Cc], s_wm[Cc], s_ws[Cc];
    int t = threadIdx.x;
    s_a[t] = g_bna[t]; s_b[t] = g_bnb[t]; s_wm[t] = Wm[t]; s_ws[t] = Ws[t];
    __syncthreads();
    int P = blockIdx.x * 256 + t;
    int tile = P >> 7, px = P & 127;
    float m = 0.f, lv = 0.f;
#pragma unroll 4
    for (int cc = 0; cc < 16; cc++) {
#pragma unroll
        for (int kg = 0; kg < 2; kg++) {
            H8 u0;
#pragma unroll
            for (int e = 0; e < 8; e++) {
                int ch = cc * 16 + kg * 8 + e;
                float v = g_h[(size_t)ch * NTOT + P];
                float r = fmaxf(fmaf(s_a[ch], v, s_b[ch]), 0.f);
                m = fmaf(s_wm[ch], r, m);
                lv = fmaf(s_ws[ch], r, lv);
                u0.h[e] = __float2half_rn(r);
            }
            int u2 = (kg ^ (px >> 2)) & 1;
            *(uint4*)(g_B2 + (size_t)(tile * 16 + cc) * 2048 + px * 16 + u2 * 8) = u0.v;
        }
    }
    float stdv = __expf(0.5f * lv);
    out[PROB_OFF + P] = fmaf(eps1[P], stdv, m);
    int b = P >> 14, hw = P & (HW - 1);
    const float* e = eps50 + (size_t)b * NS * HW + hw;
    float v[NS], s = 0.f;
#pragma unroll
    for (int i = 0; i < NS; i++) {
        float tt = fmaf(e[(size_t)i * HW], stdv, m);
        float pv = __fdividef(1.f, 1.f + __expf(-tt));
        v[i] = pv; s += pv;
    }
    float mm = s * (1.f / NS), ss = 0.f;
#pragma unroll
    for (int i = 0; i < NS; i++) { float dd = v[i] - mm; ss = fmaf(dd, dd, ss); }
    g_u[P] = ss * (1.f / (NS - 1));
}

// ---------------- 3x 7x7 box filter, banded (64 blocks), + global min/max ----------------
#define BAND 16
#define HALO 9
#define LROWS (BAND + 2*HALO)   // 34
__global__ void k_box() {
    __shared__ float s0[LROWS][128], s1[LROWS][128];
    __shared__ unsigned int smn, smx;
    const int band = blockIdx.x, b = blockIdx.y;
    const int r0 = band * BAND - HALO;     // global row of ly=0
    const int tid = threadIdx.x;
    if (tid == 0) { smn = 0xFFFFFFFFu; smx = 0u; }
    const float* up = g_u + (size_t)b * HW;
    for (int i = tid; i < LROWS * 128; i += 256) {
        int ly = i >> 7, xx = i & 127;
        int gy = r0 + ly;
        s0[ly][xx] = (gy >= 0 && gy < 128) ? up[(gy << 7) + xx] : 0.f;
    }
    __syncthreads();
    int lo = 0, hi = LROWS;
    for (int it = 0; it < 3; it++) {
        for (int i = tid; i < LROWS * 128; i += 256) {
            int ly = i >> 7, xx = i & 127;
            if (ly >= lo && ly < hi) {
                int x0 = xx - 3 < 0 ? 0 : xx - 3;
                int x1 = xx + 3 > 127 ? 127 : xx + 3;
                float s = 0.f;
                for (int x2 = x0; x2 <= x1; x2++) s += s0[ly][x2];
                s1[ly][xx] = s;
            }
        }
        __syncthreads();
        lo += 3; hi -= 3;
        for (int i = tid; i < LROWS * 128; i += 256) {
            int ly = i >> 7, xx = i & 127;
            if (ly >= lo && ly < hi) {
                int gy = r0 + ly;
                float s = 0.f;
#pragma unroll
                for (int yy = -3; yy <= 3; yy++) s += s1[ly + yy][xx];
                s0[ly][xx] = (gy >= 0 && gy < 128) ? s : 0.f;   // per-iter zero pad
            }
        }
        __syncthreads();
    }
    float lmn = 3.4e38f, lmx = -3.4e38f;
    float* op = g_u2 + (size_t)b * HW + band * BAND * 128;
    for (int i = tid; i < BAND * 128; i += 256) {
        int ly = HALO + (i >> 7), xx = i & 127;
        float v = s0[ly][xx];
        op[i] = v;
        lmn = fminf(lmn, v); lmx = fmaxf(lmx, v);
    }
    atomicMin(&smn, __float_as_uint(lmn));
    atomicMax(&smx, __float_as_uint(lmx));
    __syncthreads();
    if (tid == 0) { atomicMin(&g_minb, smn); atomicMax(&g_maxb, smx); }
}

// ---------------- launch ----------------
extern "C" void kernel_launch(void* const* d_in, const int* in_sizes, int n_in,
                              void* d_out, int out_size) {
    const float* x     = (const float*)d_in[0];
    const float* Wproj = (const float*)d_in[1];
    const float* gamma = (const float*)d_in[2];
    const float* beta  = (const float*)d_in[3];
    const float* Wconv = (const float*)d_in[4];
    const float* bconv = (const float*)d_in[5];
    const float* Wmean = (const float*)d_in[6];
    const float* Wstd  = (const float*)d_in[7];
    const float* eps1  = (const float*)d_in[8];
    const float* eps50 = (const float*)d_in[9];
    const float* randu = (const float*)d_in[10];
    float* out = (float*)d_out;

    cudaFuncSetAttribute(k_gemm<1>, cudaFuncAttributeMaxDynamicSharedMemorySize, SMEM_GEMM);
    cudaFuncSetAttribute(k_gemm<2>, cudaFuncAttributeMaxDynamicSharedMemorySize, SMEM_GEMM);

    k_prep_w<<<512, 256>>>(Wproj, Wconv);
    k_gemm<1><<<NTOT / 128, 256, SMEM_GEMM>>>(x, nullptr, nullptr, nullptr);
    k_bnfin<<<1, 256>>>(gamma, beta);
    k_fuse<<<NTOT / 256, 256>>>(Wmean, Wstd, eps1, eps50, out);
    k_box<<<dim3(Bb, Bb), 256>>>();
    k_gemm<2><<<NTOT / 64, 256, SMEM_GEMM>>>(nullptr, out, bconv, randu);
}

// round 12
// speedup vs baseline: 1.2726x; 1.0893x over previous
#include <cuda_runtime.h>
#include <cuda_fp16.h>
#include <math.h>
#include <stdint.h>

#define Cc 256
#define HW 16384
#define Bb 8
#define CHW (Cc*HW)
#define NTOT (Bb*HW)
#define TOTAL (Bb*CHW)
#define PROB_OFF TOTAL
#define NS 50

#define STG 16384            // bytes per stage: A 8KB (2 parts x 4KB) + B at 8192
#define FAC_OFF (2*STG)      // 32768
#define BIAS_OFF (FAC_OFF+512)
#define SMEM_GEMM (BIAS_OFF+1024)

// ---------------- device globals ----------------
__device__ float g_h[TOTAL];                 // h pre-BN, [ch][P] fp32
__device__ __half g_B2[TOTAL];               // relu(bn(h)) fp16, pre-swizzled chunk tiles
__device__ __half g_wA[2*2*Cc*Cc];           // weights: [gemm][part][chunk][4096]
__device__ float g_sum[Cc], g_sumsq[Cc], g_bna[Cc], g_bnb[Cc];
__device__ float g_u[NTOT], g_u2[NTOT];
__device__ unsigned int g_minb, g_maxb;

union H8 { __half h[8]; uint4 v; };

__device__ __forceinline__ uint32_t s2u(const void* p) {
    uint32_t a;
    asm("{ .reg .u64 t; cvta.to.shared.u64 t, %1; cvt.u32.u64 %0, t; }" : "=r"(a) : "l"(p));
    return a;
}
__device__ __forceinline__ void cpa16(uint32_t dst, const void* src) {
    asm volatile("cp.async.cg.shared.global [%0], [%1], 16;" :: "r"(dst), "l"(src));
}
__device__ __forceinline__ void ldmx4(uint32_t& a0, uint32_t& a1, uint32_t& a2, uint32_t& a3, uint32_t ad) {
    asm volatile("ldmatrix.sync.aligned.m8n8.x4.shared.b16 {%0,%1,%2,%3}, [%4];"
                 : "=r"(a0), "=r"(a1), "=r"(a2), "=r"(a3) : "r"(ad));
}
__device__ __forceinline__ void ldmx2(uint32_t& b0, uint32_t& b1, uint32_t ad) {
    asm volatile("ldmatrix.sync.aligned.m8n8.x2.shared.b16 {%0,%1}, [%2];"
                 : "=r"(b0), "=r"(b1) : "r"(ad));
}
__device__ __forceinline__ void mma16816(float* d, const uint32_t* a, uint32_t b0, uint32_t b1) {
    asm volatile("mma.sync.aligned.m16n8k16.row.col.f32.f16.f16.f32 "
                 "{%0,%1,%2,%3}, {%4,%5,%6,%7}, {%8,%9}, {%0,%1,%2,%3};"
                 : "+f"(d[0]), "+f"(d[1]), "+f"(d[2]), "+f"(d[3])
                 : "r"(a[0]), "r"(a[1]), "r"(a[2]), "r"(a[3]), "r"(b0), "r"(b1));
}

// ---------------- weight prep (+ per-call init, fused) ----------------
__global__ void k_prep_w(const float* __restrict__ Wp, const float* __restrict__ Wc) {
    int t = threadIdx.x;
    if (blockIdx.x == 0) {
        g_sum[t] = 0.f; g_sumsq[t] = 0.f;
        if (t == 0) { g_minb = 0xFFFFFFFFu; g_maxb = 0u; }
    }
    int idx = blockIdx.x * blockDim.x + t;             // 0..131071
    int g = idx >> 16, ch = (idx >> 8) & 255, k = idx & 255;
    float w = (g ? Wc : Wp)[ch * Cc + k];
    __half H = __float2half_rn(w);
    __half L = __float2half_rn(w - __half2float(H));
    int kc = k >> 4, kk = k & 15;
    int unit = ((kk >> 3) ^ (ch >> 2)) & 1;
    int elem = (ch * 32 + unit * 16 + (kk & 7) * 2) >> 1;
    size_t base = (size_t)((g * 2) * 16 + kc) * 4096 + elem;
    g_wA[base]         = H;
    g_wA[base + 65536] = L;     // part stride = 16 chunks * 4096
}

// ---------------- mma.sync GEMM, K=256 in 16 chunks, 2-stage, occ 2 ----------------
// Both passes: tile 128ch x 128px per CTA, M split across CTA pairs (blockIdx.x & 1).
// G=1: B = x fp32 (2-way fp16 split, 3 terms) -> g_h + BN stats
// G=2: B = g_B2 fp16 via cp.async (2 terms: AhBh+AlBh) -> out with bias + (1-u)*mask
template<int G>
__global__ __launch_bounds__(256, 2)
void k_gemm(const float* __restrict__ x, float* __restrict__ out,
            const float* __restrict__ bconv, const float* __restrict__ randu) {
    extern __shared__ __align__(16) char sm[];
    const uint32_t sb = s2u(sm);
    const int t = threadIdx.x, wid = t >> 5, lane = t & 31;
    const int tileIdx = blockIdx.x >> 1;
    const int mhalf   = blockIdx.x & 1;
    const int P0 = tileIdx * 128;
    constexpr int MT = 2;                 // 16-ch M-tiles per warp-group (128 ch total)

    const int ch0  = mhalf * 128 + (wid >> 1) * (MT * 16);
    const int ch0l = (wid >> 1) * (MT * 16);
    const int pix0w = (wid & 1) * 64;
    const int aRow = lane & 15, aUnit = lane >> 4;
    const int l15 = lane & 15;
    const int bRowOff = l15 & 7, bUnit = (l15 >> 3) & 1;
    const int px = t & 127, kg = t >> 7;       // G1 B loader: pixel + k-half

    float* s_fac  = (float*)(sm + FAC_OFF);
    float* s_bias = (float*)(sm + BIAS_OFF);
    if (G == 2) {
        if (t < 128) {
            float mn = __uint_as_float(g_minb), mx = __uint_as_float(g_maxb);
            float un = (g_u2[P0 + t] - mn) / (mx - mn);
            s_fac[t] = (1.f - un) * ((un < randu[P0 + t]) ? 1.f : 0.f);
        }
        s_bias[t] = bconv[t];
    }

    float d[MT][8][4];
#pragma unroll
    for (int i = 0; i < MT; i++)
#pragma unroll
        for (int j = 0; j < 8; j++)
#pragma unroll
            for (int e = 0; e < 4; e++) d[i][j][e] = 0.f;

    float bf[8];
    const float* xs = x + (size_t)(P0 >> 14) * CHW + (P0 & 16383) + px;

#define ISSUE_A(cc, so) do { \
    _Pragma("unroll") \
    for (int p = 0; p < 2; p++) { \
        const char* src = (const char*)g_wA + (size_t)(((G - 1) * 2 + p) * 16 + (cc)) * 8192 + mhalf * 4096 + t * 16; \
        cpa16(sb + (so) + p * 4096 + t * 16, src); \
    } \
    if (G == 2) { \
        const char* srcb = (const char*)g_B2 + ((size_t)(tileIdx * 16 + (cc)) * 4096) + t * 16; \
        cpa16(sb + (so) + 8192 + t * 16, srcb); \
    } \
    asm volatile("cp.async.commit_group;"); \
} while (0)

#define LOAD_B(cc) do { \
    if (G == 1) { \
        _Pragma("unroll") \
        for (int e = 0; e < 8; e++) bf[e] = xs[(size_t)((cc) * 16 + kg * 8 + e) * HW]; \
    } \
} while (0)

#define STORE_B(so) do { \
    if (G == 1) { \
        H8 u0, u1; \
        _Pragma("unroll") \
        for (int e = 0; e < 8; e++) { \
            u0.h[e] = __float2half_rn(bf[e]); \
            u1.h[e] = __float2half_rn(bf[e] - __half2float(u0.h[e])); \
        } \
        int u2 = (kg ^ (px >> 2)) & 1; \
        char* dst = sm + (so) + 8192 + px * 32 + u2 * 16; \
        *(uint4*)(dst) = u0.v; \
        *(uint4*)(dst + 4096) = u1.v; \
    } \
} while (0)

    // prologue: chunk 0
    LOAD_B(0);
    ISSUE_A(0, 0);
    STORE_B(0);
    asm volatile("cp.async.wait_group 0;");
    __syncthreads();

    for (int c = 0; c < 16; c++) {
        const uint32_t so_cur = (c & 1) * STG;
        const uint32_t so_nxt = ((c + 1) & 1) * STG;
        if (c < 15) {
            ISSUE_A(c + 1, so_nxt);
            LOAD_B(c + 1);
        }
        // ---- MMA on current stage ----
        {
            uint32_t Ast = sb + so_cur;
            uint32_t Bst = Ast + 8192;
            constexpr int NPB = (G == 1) ? 2 : 1;
            uint32_t Bf[NPB][8][2];
#pragma unroll
            for (int p = 0; p < NPB; p++)
#pragma unroll
                for (int nt = 0; nt < 8; nt++) {
                    int row = pix0w + nt * 8 + bRowOff;
                    uint32_t ad = Bst + p * 4096 + row * 32 + (((bUnit ^ (row >> 2)) & 1) << 4);
                    ldmx2(Bf[p][nt][0], Bf[p][nt][1], ad);
                }
#pragma unroll
            for (int mt = 0; mt < MT; mt++) {
#pragma unroll
                for (int pa = 0; pa < 2; pa++) {
                    int row = ch0l + mt * 16 + aRow;
                    uint32_t ad = Ast + pa * 4096 + row * 32 + (((aUnit ^ (row >> 2)) & 1) << 4);
                    uint32_t a[4];
                    ldmx4(a[0], a[1], a[2], a[3], ad);
                    const int nb = (G == 1) ? (2 - pa) : 1;   // G1: AhBh,AhBl,AlBh  G2: AhBh,AlBh
#pragma unroll
                    for (int pb = 0; pb < NPB; pb++) {
                        if (pb >= nb) break;
#pragma unroll
                        for (int nt = 0; nt < 8; nt++)
                            mma16816(d[mt][nt], a, Bf[pb][nt][0], Bf[pb][nt][1]);
                    }
                }
            }
        }
        if (c < 15) {
            STORE_B(so_nxt);
            asm volatile("cp.async.wait_group 0;");
        }
        __syncthreads();
    }

    // ---- epilogue ----
    const int rq = lane >> 2, q = lane & 3;
    if (G == 1) {
        float* s_sum = (float*)sm;
        float* s_sq = s_sum + 256;
        s_sum[t] = 0.f; s_sq[t] = 0.f;
        __syncthreads();
#pragma unroll
        for (int mt = 0; mt < MT; mt++) {
            int c_0 = ch0 + mt * 16 + rq, c_1 = c_0 + 8;
            float s0 = 0.f, q0 = 0.f, s1 = 0.f, q1 = 0.f;
#pragma unroll
            for (int nt = 0; nt < 8; nt++) {
                float v0 = d[mt][nt][0], v1 = d[mt][nt][1];
                float v2 = d[mt][nt][2], v3 = d[mt][nt][3];
                size_t PP = (size_t)P0 + pix0w + nt * 8 + q * 2;
                *(float2*)&g_h[(size_t)c_0 * NTOT + PP] = make_float2(v0, v1);
                *(float2*)&g_h[(size_t)c_1 * NTOT + PP] = make_float2(v2, v3);
                s0 += v0 + v1; q0 += v0 * v0 + v1 * v1;
                s1 += v2 + v3; q1 += v2 * v2 + v3 * v3;
            }
#pragma unroll
            for (int o = 1; o <= 2; o <<= 1) {
                s0 += __shfl_xor_sync(0xFFFFFFFFu, s0, o);
                q0 += __shfl_xor_sync(0xFFFFFFFFu, q0, o);
                s1 += __shfl_xor_sync(0xFFFFFFFFu, s1, o);
                q1 += __shfl_xor_sync(0xFFFFFFFFu, q1, o);
            }
            if (q == 0) {
                atomicAdd(&s_sum[c_0], s0); atomicAdd(&s_sq[c_0], q0);
                atomicAdd(&s_sum[c_1], s1); atomicAdd(&s_sq[c_1], q1);
            }
        }
        __syncthreads();
        atomicAdd(&g_sum[t], s_sum[t]);
        atomicAdd(&g_sumsq[t], s_sq[t]);
    } else {
        const size_t obase = (size_t)(P0 >> 14) * CHW + (P0 & 16383);
#pragma unroll
        for (int mt = 0; mt < MT; mt++) {
            int c_0 = ch0 + mt * 16 + rq, c_1 = c_0 + 8;
            float b0 = s_bias[c_0], b1 = s_bias[c_1];
#pragma unroll
            for (int nt = 0; nt < 8; nt++) {
                int pixL = pix0w + nt * 8 + q * 2;
                float f0 = s_fac[pixL], f1 = s_fac[pixL + 1];
                *(float2*)&out[obase + (size_t)c_0 * HW + pixL] =
                    make_float2((d[mt][nt][0] + b0) * f0, (d[mt][nt][1] + b0) * f1);
                *(float2*)&out[obase + (size_t)c_1 * HW + pixL] =
                    make_float2((d[mt][nt][2] + b1) * f0, (d[mt][nt][3] + b1) * f1);
            }
        }
    }
#undef ISSUE_A
#undef LOAD_B
#undef STORE_B
}

// ---------------- BN finalize ----------------
__global__ void k_bnfin(const float* __restrict__ gamma, const float* __restrict__ beta) {
    int c = threadIdx.x;
    float n = (float)NTOT;
    float mu = g_sum[c] / n;
    float var = fmaxf(g_sumsq[c] / n - mu * mu, 0.f);
    float a = gamma[c] * rsqrtf(var + 1e-5f);
    g_bna[c] = a; g_bnb[c] = beta[c] - mu * a;
}

// ---------------- fused: BN+ReLU -> g_B2, mean/logvar GEMV, prob_x, u (no sample array) ----------------
__global__ void k_fuse(const float* __restrict__ Wm, const float* __restrict__ Ws,
                       const float* __restrict__ eps1, const float* __restrict__ eps50,
                       float* __restrict__ out) {
    __shared__ float s_a[Cc], s_b[Cc], s_wm[Cc], s_ws[Cc];
    int t = threadIdx.x;
    s_a[t] = g_bna[t]; s_b[t] = g_bnb[t]; s_wm[t] = Wm[t]; s_ws[t] = Ws[t];
    __syncthreads();
    int P = blockIdx.x * 256 + t;
    int tile = P >> 7, px = P & 127;
    float m = 0.f, lv = 0.f;
#pragma unroll 4
    for (int cc = 0; cc < 16; cc++) {
#pragma unroll
        for (int kg = 0; kg < 2; kg++) {
            H8 u0;
#pragma unroll
            for (int e = 0; e < 8; e++) {
                int ch = cc * 16 + kg * 8 + e;
                float v = g_h[(size_t)ch * NTOT + P];
                float r = fmaxf(fmaf(s_a[ch], v, s_b[ch]), 0.f);
                m = fmaf(s_wm[ch], r, m);
                lv = fmaf(s_ws[ch], r, lv);
                u0.h[e] = __float2half_rn(r);
            }
            int u2 = (kg ^ (px >> 2)) & 1;
            *(uint4*)(g_B2 + (size_t)(tile * 16 + cc) * 2048 + px * 16 + u2 * 8) = u0.v;
        }
    }
    float stdv = __expf(0.5f * lv);
    out[PROB_OFF + P] = fmaf(eps1[P], stdv, m);
    int b = P >> 14, hw = P & (HW - 1);
    const float* e = eps50 + (size_t)b * NS * HW + hw;
    // single-pass shifted variance: q = sigmoid(t) - 0.5 keeps s2 ~ var (no cancellation)
    float s = 0.f, s2 = 0.f;
#pragma unroll
    for (int i = 0; i < NS; i++) {
        float tt = fmaf(e[(size_t)i * HW], stdv, m);
        float pv = __fdividef(1.f, 1.f + __expf(-tt));
        float qv = pv - 0.5f;
        s += qv; s2 = fmaf(qv, qv, s2);
    }
    g_u[P] = (s2 - s * s * (1.f / NS)) * (1.f / (NS - 1));
}

// ---------------- 3x 7x7 box filter, banded (64 blocks), + global min/max ----------------
#define BAND 16
#define HALO 9
#define LROWS (BAND + 2*HALO)   // 34
__global__ void k_box() {
    __shared__ float s0[LROWS][128], s1[LROWS][128];
    __shared__ unsigned int smn, smx;
    const int band = blockIdx.x, b = blockIdx.y;
    const int r0 = band * BAND - HALO;     // global row of ly=0
    const int tid = threadIdx.x;
    if (tid == 0) { smn = 0xFFFFFFFFu; smx = 0u; }
    const float* up = g_u + (size_t)b * HW;
    for (int i = tid; i < LROWS * 128; i += 256) {
        int ly = i >> 7, xx = i & 127;
        int gy = r0 + ly;
        s0[ly][xx] = (gy >= 0 && gy < 128) ? up[(gy << 7) + xx] : 0.f;
    }
    __syncthreads();
    int lo = 0, hi = LROWS;
    for (int it = 0; it < 3; it++) {
        for (int i = tid; i < LROWS * 128; i += 256) {
            int ly = i >> 7, xx = i & 127;
            if (ly >= lo && ly < hi) {
                int x0 = xx - 3 < 0 ? 0 : xx - 3;
                int x1 = xx + 3 > 127 ? 127 : xx + 3;
                float s = 0.f;
                for (int x2 = x0; x2 <= x1; x2++) s += s0[ly][x2];
                s1[ly][xx] = s;
            }
        }
        __syncthreads();
        lo += 3; hi -= 3;
        for (int i = tid; i < LROWS * 128; i += 256) {
            int ly = i >> 7, xx = i & 127;
            if (ly >= lo && ly < hi) {
                int gy = r0 + ly;
                float s = 0.f;
#pragma unroll
                for (int yy = -3; yy <= 3; yy++) s += s1[ly + yy][xx];
                s0[ly][xx] = (gy >= 0 && gy < 128) ? s : 0.f;   // per-iter zero pad
            }
        }
        __syncthreads();
    }
    float lmn = 3.4e38f, lmx = -3.4e38f;
    float* op = g_u2 + (size_t)b * HW + band * BAND * 128;
    for (int i = tid; i < BAND * 128; i += 256) {
        int ly = HALO + (i >> 7), xx = i & 127;
        float v = s0[ly][xx];
        op[i] = v;
        lmn = fminf(lmn, v); lmx = fmaxf(lmx, v);
    }
    atomicMin(&smn, __float_as_uint(lmn));
    atomicMax(&smx, __float_as_uint(lmx));
    __syncthreads();
    if (tid == 0) { atomicMin(&g_minb, smn); atomicMax(&g_maxb, smx); }
}

// ---------------- launch ----------------
extern "C" void kernel_launch(void* const* d_in, const int* in_sizes, int n_in,
                              void* d_out, int out_size) {
    const float* x     = (const float*)d_in[0];
    const float* Wproj = (const float*)d_in[1];
    const float* gamma = (const float*)d_in[2];
    const float* beta  = (const float*)d_in[3];
    const float* Wconv = (const float*)d_in[4];
    const float* bconv = (const float*)d_in[5];
    const float* Wmean = (const float*)d_in[6];
    const float* Wstd  = (const float*)d_in[7];
    const float* eps1  = (const float*)d_in[8];
    const float* eps50 = (const float*)d_in[9];
    const float* randu = (const float*)d_in[10];
    float* out = (float*)d_out;

    cudaFuncSetAttribute(k_gemm<1>, cudaFuncAttributeMaxDynamicSharedMemorySize, SMEM_GEMM);
    cudaFuncSetAttribute(k_gemm<2>, cudaFuncAttributeMaxDynamicSharedMemorySize, SMEM_GEMM);

    k_prep_w<<<512, 256>>>(Wproj, Wconv);
    k_gemm<1><<<NTOT / 64, 256, SMEM_GEMM>>>(x, nullptr, nullptr, nullptr);
    k_bnfin<<<1, 256>>>(gamma, beta);
    k_fuse<<<NTOT / 256, 256>>>(Wmean, Wstd, eps1, eps50, out);
    k_box<<<dim3(Bb, Bb), 256>>>();
    k_gemm<2><<<NTOT / 64, 256, SMEM_GEMM>>>(nullptr, out, bconv, randu);
}

// round 13
// speedup vs baseline: 1.2832x; 1.0083x over previous
#include <cuda_runtime.h>
#include <cuda_fp16.h>
#include <math.h>
#include <stdint.h>

#define Cc 256
#define HW 16384
#define Bb 8
#define CHW (Cc*HW)
#define NTOT (Bb*HW)
#define TOTAL (Bb*CHW)
#define PROB_OFF TOTAL
#define NS 50

// per-pass stage sizes: G1 = A 16KB + B 2x2KB = 20KB; G2 = A 2x4KB + B 4KB = 12KB
#define FAC_OFF 40960
#define BIAS_OFF (FAC_OFF+512)
#define SMEM_GEMM (BIAS_OFF+1024)

// ---------------- device globals ----------------
__device__ float g_h[TOTAL];                 // h pre-BN, [ch][P] fp32
__device__ __half g_B2[TOTAL];               // relu(bn(h)) fp16, pre-swizzled chunk tiles
__device__ __half g_wA[2*2*Cc*Cc];           // weights: [gemm][part][chunk][4096]
__device__ float g_sum[Cc], g_sumsq[Cc], g_bna[Cc], g_bnb[Cc];
__device__ float g_u[NTOT], g_u2[NTOT];
__device__ unsigned int g_minb, g_maxb;

union H8 { __half h[8]; uint4 v; };
union H4 { __half h[4]; uint2 v; };

__device__ __forceinline__ uint32_t s2u(const void* p) {
    uint32_t a;
    asm("{ .reg .u64 t; cvta.to.shared.u64 t, %1; cvt.u32.u64 %0, t; }" : "=r"(a) : "l"(p));
    return a;
}
__device__ __forceinline__ void cpa16(uint32_t dst, const void* src) {
    asm volatile("cp.async.cg.shared.global [%0], [%1], 16;" :: "r"(dst), "l"(src));
}
__device__ __forceinline__ void ldmx4(uint32_t& a0, uint32_t& a1, uint32_t& a2, uint32_t& a3, uint32_t ad) {
    asm volatile("ldmatrix.sync.aligned.m8n8.x4.shared.b16 {%0,%1,%2,%3}, [%4];"
                 : "=r"(a0), "=r"(a1), "=r"(a2), "=r"(a3) : "r"(ad));
}
__device__ __forceinline__ void ldmx2(uint32_t& b0, uint32_t& b1, uint32_t ad) {
    asm volatile("ldmatrix.sync.aligned.m8n8.x2.shared.b16 {%0,%1}, [%2];"
                 : "=r"(b0), "=r"(b1) : "r"(ad));
}
__device__ __forceinline__ void mma16816(float* d, const uint32_t* a, uint32_t b0, uint32_t b1) {
    asm volatile("mma.sync.aligned.m16n8k16.row.col.f32.f16.f16.f32 "
                 "{%0,%1,%2,%3}, {%4,%5,%6,%7}, {%8,%9}, {%0,%1,%2,%3};"
                 : "+f"(d[0]), "+f"(d[1]), "+f"(d[2]), "+f"(d[3])
                 : "r"(a[0]), "r"(a[1]), "r"(a[2]), "r"(a[3]), "r"(b0), "r"(b1));
}

// ---------------- weight prep (+ per-call init, fused) ----------------
__global__ void k_prep_w(const float* __restrict__ Wp, const float* __restrict__ Wc) {
    int t = threadIdx.x;
    if (blockIdx.x == 0) {
        g_sum[t] = 0.f; g_sumsq[t] = 0.f;
        if (t == 0) { g_minb = 0xFFFFFFFFu; g_maxb = 0u; }
    }
    int idx = blockIdx.x * blockDim.x + t;             // 0..131071
    int g = idx >> 16, ch = (idx >> 8) & 255, k = idx & 255;
    float w = (g ? Wc : Wp)[ch * Cc + k];
    __half H = __float2half_rn(w);
    __half L = __float2half_rn(w - __half2float(H));
    int kc = k >> 4, kk = k & 15;
    int unit = ((kk >> 3) ^ (ch >> 2)) & 1;
    int elem = (ch * 32 + unit * 16 + (kk & 7) * 2) >> 1;
    size_t base = (size_t)((g * 2) * 16 + kc) * 4096 + elem;
    g_wA[base]         = H;
    g_wA[base + 65536] = L;     // part stride = 16 chunks * 4096
}

// ---------------- mma.sync GEMM, K=256 in 16 chunks, 2-stage, occ 2 ----------------
// G=1: N-SPLIT. tile 256ch x 64px per CTA (grid NTOT/64). B = x fp32 (2-way fp16
//      split, 3 terms) -> g_h + BN stats. No duplicated B conversion.
// G=2: M-SPLIT. tile 128ch x 128px per CTA pair. B = g_B2 fp16 via cp.async
//      (2 terms: AhBh+AlBh) -> out with bias + (1-u)*mask
template<int G>
__global__ __launch_bounds__(256, 2)
void k_gemm(const float* __restrict__ x, float* __restrict__ out,
            const float* __restrict__ bconv, const float* __restrict__ randu) {
    extern __shared__ __align__(16) char sm[];
    const uint32_t sb = s2u(sm);
    const int t = threadIdx.x, wid = t >> 5, lane = t & 31;

    constexpr int STGG = (G == 1) ? 20480 : 12288;  // stage bytes
    constexpr int MT   = (G == 1) ? 4 : 2;          // 16-ch M-tiles per warp
    constexpr int NT   = (G == 1) ? 4 : 8;          // 8-px N-tiles per warp
    constexpr int APS  = (G == 1) ? 8192 : 4096;    // A part stride in stage
    constexpr int BOF  = (G == 1) ? 16384 : 8192;   // B offset in stage
    constexpr int BPS  = (G == 1) ? 2048 : 4096;    // B part stride

    const int tileIdx = (G == 1) ? blockIdx.x : (blockIdx.x >> 1);
    const int mhalf   = (G == 1) ? 0 : (blockIdx.x & 1);
    const int P0      = (G == 1) ? tileIdx * 64 : tileIdx * 128;

    const int ch0l  = (wid >> 1) * (MT * 16);
    const int ch0   = mhalf * 128 + ch0l;
    const int pix0w = (wid & 1) * (NT * 8);
    const int aRow = lane & 15, aUnit = lane >> 4;
    const int l15 = lane & 15;
    const int bRowOff = l15 & 7, bUnit = (l15 >> 3) & 1;
    // G1 B loader: 64 px x 4 k-segments
    const int px = t & 63, kseg = t >> 6;

    float* s_fac  = (float*)(sm + FAC_OFF);
    float* s_bias = (float*)(sm + BIAS_OFF);
    if (G == 2) {
        if (t < 128) {
            float mn = __uint_as_float(g_minb), mx = __uint_as_float(g_maxb);
            float un = (g_u2[P0 + t] - mn) / (mx - mn);
            s_fac[t] = (1.f - un) * ((un < randu[P0 + t]) ? 1.f : 0.f);
        }
        s_bias[t] = bconv[t];
    }

    float d[MT][NT][4];
#pragma unroll
    for (int i = 0; i < MT; i++)
#pragma unroll
        for (int j = 0; j < NT; j++)
#pragma unroll
            for (int e = 0; e < 4; e++) d[i][j][e] = 0.f;

    float bf[4];
    const float* xs = x + (size_t)(P0 >> 14) * CHW + (P0 & 16383) + px;

#define ISSUE_A(cc, so) do { \
    if (G == 1) { \
        _Pragma("unroll") \
        for (int i = 0; i < 4; i++) { \
            int u = t + i * 256; \
            int p = u >> 9, w = u & 511; \
            const char* src = (const char*)g_wA + (size_t)(p * 16 + (cc)) * 8192 + w * 16; \
            cpa16(sb + (so) + p * 8192 + w * 16, src); \
        } \
    } else { \
        _Pragma("unroll") \
        for (int p = 0; p < 2; p++) { \
            const char* src = (const char*)g_wA + (size_t)((2 + p) * 16 + (cc)) * 8192 + mhalf * 4096 + t * 16; \
            cpa16(sb + (so) + p * 4096 + t * 16, src); \
        } \
        const char* srcb = (const char*)g_B2 + ((size_t)(tileIdx * 16 + (cc)) * 4096) + t * 16; \
        cpa16(sb + (so) + BOF + t * 16, srcb); \
    } \
    asm volatile("cp.async.commit_group;"); \
} while (0)

#define LOAD_B(cc) do { \
    if (G == 1) { \
        _Pragma("unroll") \
        for (int e = 0; e < 4; e++) bf[e] = xs[(size_t)((cc) * 16 + kseg * 4 + e) * HW]; \
    } \
} while (0)

#define STORE_B(so) do { \
    if (G == 1) { \
        H4 u0, u1; \
        _Pragma("unroll") \
        for (int e = 0; e < 4; e++) { \
            u0.h[e] = __float2half_rn(bf[e]); \
            u1.h[e] = __float2half_rn(bf[e] - __half2float(u0.h[e])); \
        } \
        int sunit = (kseg >> 1) ^ ((px >> 2) & 1); \
        char* dst = sm + (so) + BOF + px * 32 + sunit * 16 + (kseg & 1) * 8; \
        *(uint2*)(dst) = u0.v; \
        *(uint2*)(dst + BPS) = u1.v; \
    } \
} while (0)

    // prologue: chunk 0
    LOAD_B(0);
    ISSUE_A(0, 0);
    STORE_B(0);
    asm volatile("cp.async.wait_group 0;");
    __syncthreads();

    for (int c = 0; c < 16; c++) {
        const uint32_t so_cur = (c & 1) * STGG;
        const uint32_t so_nxt = ((c + 1) & 1) * STGG;
        if (c < 15) {
            ISSUE_A(c + 1, so_nxt);
            LOAD_B(c + 1);
        }
        // ---- MMA on current stage ----
        {
            uint32_t Ast = sb + so_cur;
            uint32_t Bst = Ast + BOF;
            constexpr int NPB = (G == 1) ? 2 : 1;
            uint32_t Bf[NPB][NT][2];
#pragma unroll
            for (int p = 0; p < NPB; p++)
#pragma unroll
                for (int nt = 0; nt < NT; nt++) {
                    int row = pix0w + nt * 8 + bRowOff;
                    uint32_t ad = Bst + p * BPS + row * 32 + (((bUnit ^ (row >> 2)) & 1) << 4);
                    ldmx2(Bf[p][nt][0], Bf[p][nt][1], ad);
                }
#pragma unroll
            for (int mt = 0; mt < MT; mt++) {
#pragma unroll
                for (int pa = 0; pa < 2; pa++) {
                    int row = ch0l + mt * 16 + aRow;
                    uint32_t ad = Ast + pa * APS + row * 32 + (((aUnit ^ (row >> 2)) & 1) << 4);
                    uint32_t a[4];
                    ldmx4(a[0], a[1], a[2], a[3], ad);
                    const int nb = (G == 1) ? (2 - pa) : 1;   // G1: AhBh,AhBl,AlBh  G2: AhBh,AlBh
#pragma unroll
                    for (int pb = 0; pb < NPB; pb++) {
                        if (pb >= nb) break;
#pragma unroll
                        for (int nt = 0; nt < NT; nt++)
                            mma16816(d[mt][nt], a, Bf[pb][nt][0], Bf[pb][nt][1]);
                    }
                }
            }
        }
        if (c < 15) {
            STORE_B(so_nxt);
            asm volatile("cp.async.wait_group 0;");
        }
        __syncthreads();
    }

    // ---- epilogue ----
    const int rq = lane >> 2, q = lane & 3;
    if (G == 1) {
        float* s_sum = (float*)sm;
        float* s_sq = s_sum + 256;
        s_sum[t] = 0.f; s_sq[t] = 0.f;
        __syncthreads();
#pragma unroll
        for (int mt = 0; mt < MT; mt++) {
            int c_0 = ch0 + mt * 16 + rq, c_1 = c_0 + 8;
            float s0 = 0.f, q0 = 0.f, s1 = 0.f, q1 = 0.f;
#pragma unroll
            for (int nt = 0; nt < NT; nt++) {
                float v0 = d[mt][nt][0], v1 = d[mt][nt][1];
                float v2 = d[mt][nt][2], v3 = d[mt][nt][3];
                size_t PP = (size_t)P0 + pix0w + nt * 8 + q * 2;
                *(float2*)&g_h[(size_t)c_0 * NTOT + PP] = make_float2(v0, v1);
                *(float2*)&g_h[(size_t)c_1 * NTOT + PP] = make_float2(v2, v3);
                s0 += v0 + v1; q0 += v0 * v0 + v1 * v1;
                s1 += v2 + v3; q1 += v2 * v2 + v3 * v3;
            }
#pragma unroll
            for (int o = 1; o <= 2; o <<= 1) {
                s0 += __shfl_xor_sync(0xFFFFFFFFu, s0, o);
                q0 += __shfl_xor_sync(0xFFFFFFFFu, q0, o);
                s1 += __shfl_xor_sync(0xFFFFFFFFu, s1, o);
                q1 += __shfl_xor_sync(0xFFFFFFFFu, q1, o);
            }
            if (q == 0) {
                atomicAdd(&s_sum[c_0], s0); atomicAdd(&s_sq[c_0], q0);
                atomicAdd(&s_sum[c_1], s1); atomicAdd(&s_sq[c_1], q1);
            }
        }
        __syncthreads();
        atomicAdd(&g_sum[t], s_sum[t]);
        atomicAdd(&g_sumsq[t], s_sq[t]);
    } else {
        const size_t obase = (size_t)(P0 >> 14) * CHW + (P0 & 16383);
#pragma unroll
        for (int mt = 0; mt < MT; mt++) {
            int c_0 = ch0 + mt * 16 + rq, c_1 = c_0 + 8;
            float b0 = s_bias[c_0], b1 = s_bias[c_1];
#pragma unroll
            for (int nt = 0; nt < NT; nt++) {
                int pixL = pix0w + nt * 8 + q * 2;
                float f0 = s_fac[pixL], f1 = s_fac[pixL + 1];
                *(float2*)&out[obase + (size_t)c_0 * HW + pixL] =
                    make_float2((d[mt][nt][0] + b0) * f0, (d[mt][nt][1] + b0) * f1);
                *(float2*)&out[obase + (size_t)c_1 * HW + pixL] =
                    make_float2((d[mt][nt][2] + b1) * f0, (d[mt][nt][3] + b1) * f1);
            }
        }
    }
#undef ISSUE_A
#undef LOAD_B
#undef STORE_B
}

// ---------------- BN finalize ----------------
__global__ void k_bnfin(const float* __restrict__ gamma, const float* __restrict__ beta) {
    int c = threadIdx.x;
    float n = (float)NTOT;
    float mu = g_sum[c] / n;
    float var = fmaxf(g_sumsq[c] / n - mu * mu, 0.f);
    float a = gamma[c] * rsqrtf(var + 1e-5f);
    g_bna[c] = a; g_bnb[c] = beta[c] - mu * a;
}

// ---------------- fused: BN+ReLU -> g_B2, mean/logvar GEMV, prob_x, u ----------------
__global__ void k_fuse(const float* __restrict__ Wm, const float* __restrict__ Ws,
                       const float* __restrict__ eps1, const float* __restrict__ eps50,
                       float* __restrict__ out) {
    __shared__ float s_a[Cc], s_b[Cc], s_wm[Cc], s_ws[Cc];
    int t = threadIdx.x;
    s_a[t] = g_bna[t]; s_b[t] = g_bnb[t]; s_wm[t] = Wm[t]; s_ws[t] = Ws[t];
    __syncthreads();
    int P = blockIdx.x * 256 + t;
    int tile = P >> 7, px = P & 127;
    float m = 0.f, lv = 0.f;
#pragma unroll 4
    for (int cc = 0; cc < 16; cc++) {
#pragma unroll
        for (int kg = 0; kg < 2; kg++) {
            H8 u0;
#pragma unroll
            for (int e = 0; e < 8; e++) {
                int ch = cc * 16 + kg * 8 + e;
                float v = g_h[(size_t)ch * NTOT + P];
                float r = fmaxf(fmaf(s_a[ch], v, s_b[ch]), 0.f);
                m = fmaf(s_wm[ch], r, m);
                lv = fmaf(s_ws[ch], r, lv);
                u0.h[e] = __float2half_rn(r);
            }
            int u2 = (kg ^ (px >> 2)) & 1;
            *(uint4*)(g_B2 + (size_t)(tile * 16 + cc) * 2048 + px * 16 + u2 * 8) = u0.v;
        }
    }
    float stdv = __expf(0.5f * lv);
    out[PROB_OFF + P] = fmaf(eps1[P], stdv, m);
    int b = P >> 14, hw = P & (HW - 1);
    const float* e = eps50 + (size_t)b * NS * HW + hw;
    float s = 0.f, s2 = 0.f;
#pragma unroll
    for (int i = 0; i < NS; i++) {
        float tt = fmaf(e[(size_t)i * HW], stdv, m);
        float pv = __fdividef(1.f, 1.f + __expf(-tt));
        float qv = pv - 0.5f;
        s += qv; s2 = fmaf(qv, qv, s2);
    }
    g_u[P] = (s2 - s * s * (1.f / NS)) * (1.f / (NS - 1));
}

// ---------------- 3x 7x7 box filter, banded (64 blocks), + global min/max ----------------
#define BAND 16
#define HALO 9
#define LROWS (BAND + 2*HALO)   // 34
__global__ void k_box() {
    __shared__ float s0[LROWS][128], s1[LROWS][128];
    __shared__ unsigned int smn, smx;
    const int band = blockIdx.x, b = blockIdx.y;
    const int r0 = band * BAND - HALO;     // global row of ly=0
    const int tid = threadIdx.x;
    if (tid == 0) { smn = 0xFFFFFFFFu; smx = 0u; }
    const float* up = g_u + (size_t)b * HW;
    for (int i = tid; i < LROWS * 128; i += 256) {
        int ly = i >> 7, xx = i & 127;
        int gy = r0 + ly;
        s0[ly][xx] = (gy >= 0 && gy < 128) ? up[(gy << 7) + xx] : 0.f;
    }
    __syncthreads();
    int lo = 0, hi = LROWS;
    for (int it = 0; it < 3; it++) {
        for (int i = tid; i < LROWS * 128; i += 256) {
            int ly = i >> 7, xx = i & 127;
            if (ly >= lo && ly < hi) {
                int x0 = xx - 3 < 0 ? 0 : xx - 3;
                int x1 = xx + 3 > 127 ? 127 : xx + 3;
                float s = 0.f;
                for (int x2 = x0; x2 <= x1; x2++) s += s0[ly][x2];
                s1[ly][xx] = s;
            }
        }
        __syncthreads();
        lo += 3; hi -= 3;
        for (int i = tid; i < LROWS * 128; i += 256) {
            int ly = i >> 7, xx = i & 127;
            if (ly >= lo && ly < hi) {
                int gy = r0 + ly;
                float s = 0.f;
#pragma unroll
                for (int yy = -3; yy <= 3; yy++) s += s1[ly + yy][xx];
                s0[ly][xx] = (gy >= 0 && gy < 128) ? s : 0.f;   // per-iter zero pad
            }
        }
        __syncthreads();
    }
    float lmn = 3.4e38f, lmx = -3.4e38f;
    float* op = g_u2 + (size_t)b * HW + band * BAND * 128;
    for (int i = tid; i < BAND * 128; i += 256) {
        int ly = HALO + (i >> 7), xx = i & 127;
        float v = s0[ly][xx];
        op[i] = v;
        lmn = fminf(lmn, v); lmx = fmaxf(lmx, v);
    }
    atomicMin(&smn, __float_as_uint(lmn));
    atomicMax(&smx, __float_as_uint(lmx));
    __syncthreads();
    if (tid == 0) { atomicMin(&g_minb, smn); atomicMax(&g_maxb, smx); }
}

// ---------------- launch ----------------
extern "C" void kernel_launch(void* const* d_in, const int* in_sizes, int n_in,
                              void* d_out, int out_size) {
    const float* x     = (const float*)d_in[0];
    const float* Wproj = (const float*)d_in[1];
    const float* gamma = (const float*)d_in[2];
    const float* beta  = (const float*)d_in[3];
    const float* Wconv = (const float*)d_in[4];
    const float* bconv = (const float*)d_in[5];
    const float* Wmean = (const float*)d_in[6];
    const float* Wstd  = (const float*)d_in[7];
    const float* eps1  = (const float*)d_in[8];
    const float* eps50 = (const float*)d_in[9];
    const float* randu = (const float*)d_in[10];
    float* out = (float*)d_out;

    cudaFuncSetAttribute(k_gemm<1>, cudaFuncAttributeMaxDynamicSharedMemorySize, SMEM_GEMM);
    cudaFuncSetAttribute(k_gemm<2>, cudaFuncAttributeMaxDynamicSharedMemorySize, SMEM_GEMM);

    k_prep_w<<<512, 256>>>(Wproj, Wconv);
    k_gemm<1><<<NTOT / 64, 256, SMEM_GEMM>>>(x, nullptr, nullptr, nullptr);
    k_bnfin<<<1, 256>>>(gamma, beta);
    k_fuse<<<NTOT / 256, 256>>>(Wmean, Wstd, eps1, eps50, out);
    k_box<<<dim3(Bb, Bb), 256>>>();
    k_gemm<2><<<NTOT / 64, 256, SMEM_GEMM>>>(nullptr, out, bconv, randu);
}

// round 14
// speedup vs baseline: 1.3592x; 1.0593x over previous
#include <cuda_runtime.h>
#include <cuda_fp16.h>
#include <math.h>
#include <stdint.h>

#define Cc 256
#define HW 16384
#define Bb 8
#define CHW (Cc*HW)
#define NTOT (Bb*HW)
#define TOTAL (Bb*CHW)
#define PROB_OFF TOTAL
#define NS 50

// G1: stage = A 16KB + B 2x2KB = 20KB. G2: stage = A 4KB + B 4KB = 8KB.
#define SMEM_G1 (2*20480 + 2048)
#define SMEM_G2 (2*8192  + 2048)

// ---------------- device globals ----------------
__device__ float g_h[TOTAL];                 // h pre-BN, [ch][P] fp32
__device__ __half g_B2[TOTAL];               // relu(bn(h)) fp16, pre-swizzled chunk tiles
__device__ __half g_wA[2*2*Cc*Cc];           // weights: [gemm][part][chunk][4096]
__device__ float g_sum[Cc], g_sumsq[Cc];
__device__ float g_u[NTOT], g_u2[NTOT];
__device__ unsigned int g_minb, g_maxb;

union H8 { __half h[8]; uint4 v; };
union H4 { __half h[4]; uint2 v; };

__device__ __forceinline__ uint32_t s2u(const void* p) {
    uint32_t a;
    asm("{ .reg .u64 t; cvta.to.shared.u64 t, %1; cvt.u32.u64 %0, t; }" : "=r"(a) : "l"(p));
    return a;
}
__device__ __forceinline__ void cpa16(uint32_t dst, const void* src) {
    asm volatile("cp.async.cg.shared.global [%0], [%1], 16;" :: "r"(dst), "l"(src));
}
__device__ __forceinline__ void ldmx4(uint32_t& a0, uint32_t& a1, uint32_t& a2, uint32_t& a3, uint32_t ad) {
    asm volatile("ldmatrix.sync.aligned.m8n8.x4.shared.b16 {%0,%1,%2,%3}, [%4];"
                 : "=r"(a0), "=r"(a1), "=r"(a2), "=r"(a3) : "r"(ad));
}
__device__ __forceinline__ void ldmx2(uint32_t& b0, uint32_t& b1, uint32_t ad) {
    asm volatile("ldmatrix.sync.aligned.m8n8.x2.shared.b16 {%0,%1}, [%2];"
                 : "=r"(b0), "=r"(b1) : "r"(ad));
}
__device__ __forceinline__ void mma16816(float* d, const uint32_t* a, uint32_t b0, uint32_t b1) {
    asm volatile("mma.sync.aligned.m16n8k16.row.col.f32.f16.f16.f32 "
                 "{%0,%1,%2,%3}, {%4,%5,%6,%7}, {%8,%9}, {%0,%1,%2,%3};"
                 : "+f"(d[0]), "+f"(d[1]), "+f"(d[2]), "+f"(d[3])
                 : "r"(a[0]), "r"(a[1]), "r"(a[2]), "r"(a[3]), "r"(b0), "r"(b1));
}

// ---------------- weight prep (+ per-call init, fused) ----------------
__global__ void k_prep_w(const float* __restrict__ Wp, const float* __restrict__ Wc) {
    int t = threadIdx.x;
    if (blockIdx.x == 0) {
        g_sum[t] = 0.f; g_sumsq[t] = 0.f;
        if (t == 0) { g_minb = 0xFFFFFFFFu; g_maxb = 0u; }
    }
    int idx = blockIdx.x * blockDim.x + t;             // 0..131071
    int g = idx >> 16, ch = (idx >> 8) & 255, k = idx & 255;
    float w = (g ? Wc : Wp)[ch * Cc + k];
    __half H = __float2half_rn(w);
    __half L = __float2half_rn(w - __half2float(H));
    int kc = k >> 4, kk = k & 15;
    int unit = ((kk >> 3) ^ (ch >> 2)) & 1;
    int elem = (ch * 32 + unit * 16 + (kk & 7) * 2) >> 1;
    size_t base = (size_t)((g * 2) * 16 + kc) * 4096 + elem;
    g_wA[base]         = H;
    g_wA[base + 65536] = L;     // part stride = 16 chunks * 4096
}

// ---------------- mma.sync GEMM, K=256 in 16 chunks, 2-stage, occ>=2 ----------------
// G=1: N-SPLIT. tile 256ch x 64px per CTA. B = x fp32 (2-way fp16 split, 3 terms)
//      -> g_h + BN stats.
// G=2: M-SPLIT. tile 128ch x 128px per CTA pair. SINGLE TERM Ah*Bh, B = g_B2 via
//      cp.async -> out with bias + (1-u)*mask
template<int G>
__global__ __launch_bounds__(256, 2)
void k_gemm(const float* __restrict__ x, float* __restrict__ out,
            const float* __restrict__ bconv, const float* __restrict__ randu) {
    extern __shared__ __align__(16) char sm[];
    const uint32_t sb = s2u(sm);
    const int t = threadIdx.x, wid = t >> 5, lane = t & 31;

    constexpr int STGG = (G == 1) ? 20480 : 8192;   // stage bytes
    constexpr int MT   = (G == 1) ? 4 : 2;          // 16-ch M-tiles per warp
    constexpr int NT   = (G == 1) ? 4 : 8;          // 8-px N-tiles per warp
    constexpr int BOF  = (G == 1) ? 16384 : 4096;   // B offset in stage
    constexpr int BPS  = 2048;                      // G1 B part stride
    constexpr int FACO = 2 * STGG;

    const int tileIdx = (G == 1) ? blockIdx.x : (blockIdx.x >> 1);
    const int mhalf   = (G == 1) ? 0 : (blockIdx.x & 1);
    const int P0      = (G == 1) ? tileIdx * 64 : tileIdx * 128;

    const int ch0l  = (wid >> 1) * (MT * 16);
    const int ch0   = mhalf * 128 + ch0l;
    const int pix0w = (wid & 1) * (NT * 8);
    const int aRow = lane & 15, aUnit = lane >> 4;
    const int l15 = lane & 15;
    const int bRowOff = l15 & 7, bUnit = (l15 >> 3) & 1;
    const int px = t & 63, kseg = t >> 6;          // G1 B loader

    float* s_fac  = (float*)(sm + FACO);
    float* s_bias = (float*)(sm + FACO + 512);
    if (G == 2) {
        if (t < 128) {
            float mn = __uint_as_float(g_minb), mx = __uint_as_float(g_maxb);
            float un = (g_u2[P0 + t] - mn) / (mx - mn);
            s_fac[t] = (1.f - un) * ((un < randu[P0 + t]) ? 1.f : 0.f);
        }
        s_bias[t] = bconv[t];
    }

    float d[MT][NT][4];
#pragma unroll
    for (int i = 0; i < MT; i++)
#pragma unroll
        for (int j = 0; j < NT; j++)
#pragma unroll
            for (int e = 0; e < 4; e++) d[i][j][e] = 0.f;

    float bf[4];
    const float* xs = x + (size_t)(P0 >> 14) * CHW + (P0 & 16383) + px;

#define ISSUE_A(cc, so) do { \
    if (G == 1) { \
        _Pragma("unroll") \
        for (int i = 0; i < 4; i++) { \
            int u = t + i * 256; \
            int p = u >> 9, w = u & 511; \
            const char* src = (const char*)g_wA + (size_t)(p * 16 + (cc)) * 8192 + w * 16; \
            cpa16(sb + (so) + p * 8192 + w * 16, src); \
        } \
    } else { \
        const char* src = (const char*)g_wA + (size_t)(2 * 16 + (cc)) * 8192 + mhalf * 4096 + t * 16; \
        cpa16(sb + (so) + t * 16, src); \
        const char* srcb = (const char*)g_B2 + ((size_t)(tileIdx * 16 + (cc)) * 4096) + t * 16; \
        cpa16(sb + (so) + BOF + t * 16, srcb); \
    } \
    asm volatile("cp.async.commit_group;"); \
} while (0)

#define LOAD_B(cc) do { \
    if (G == 1) { \
        _Pragma("unroll") \
        for (int e = 0; e < 4; e++) bf[e] = xs[(size_t)((cc) * 16 + kseg * 4 + e) * HW]; \
    } \
} while (0)

#define STORE_B(so) do { \
    if (G == 1) { \
        H4 u0, u1; \
        _Pragma("unroll") \
        for (int e = 0; e < 4; e++) { \
            u0.h[e] = __float2half_rn(bf[e]); \
            u1.h[e] = __float2half_rn(bf[e] - __half2float(u0.h[e])); \
        } \
        int sunit = (kseg >> 1) ^ ((px >> 2) & 1); \
        char* dst = sm + (so) + BOF + px * 32 + sunit * 16 + (kseg & 1) * 8; \
        *(uint2*)(dst) = u0.v; \
        *(uint2*)(dst + BPS) = u1.v; \
    } \
} while (0)

    // prologue: chunk 0
    LOAD_B(0);
    ISSUE_A(0, 0);
    STORE_B(0);
    asm volatile("cp.async.wait_group 0;");
    __syncthreads();

    for (int c = 0; c < 16; c++) {
        const uint32_t so_cur = (c & 1) * STGG;
        const uint32_t so_nxt = ((c + 1) & 1) * STGG;
        if (c < 15) {
            ISSUE_A(c + 1, so_nxt);
            LOAD_B(c + 1);
        }
        // ---- MMA on current stage ----
        {
            uint32_t Ast = sb + so_cur;
            uint32_t Bst = Ast + BOF;
            constexpr int NPB = (G == 1) ? 2 : 1;
            constexpr int NPA = (G == 1) ? 2 : 1;
            uint32_t Bf[NPB][NT][2];
#pragma unroll
            for (int p = 0; p < NPB; p++)
#pragma unroll
                for (int nt = 0; nt < NT; nt++) {
                    int row = pix0w + nt * 8 + bRowOff;
                    uint32_t ad = Bst + p * BPS + row * 32 + (((bUnit ^ (row >> 2)) & 1) << 4);
                    ldmx2(Bf[p][nt][0], Bf[p][nt][1], ad);
                }
#pragma unroll
            for (int mt = 0; mt < MT; mt++) {
#pragma unroll
                for (int pa = 0; pa < NPA; pa++) {
                    int row = ch0l + mt * 16 + aRow;
                    uint32_t ad = Ast + pa * 8192 + row * 32 + (((aUnit ^ (row >> 2)) & 1) << 4);
                    uint32_t a[4];
                    ldmx4(a[0], a[1], a[2], a[3], ad);
                    const int nb = (G == 1) ? (2 - pa) : 1;   // G1: AhBh,AhBl,AlBh  G2: AhBh
#pragma unroll
                    for (int pb = 0; pb < NPB; pb++) {
                        if (pb >= nb) break;
#pragma unroll
                        for (int nt = 0; nt < NT; nt++)
                            mma16816(d[mt][nt], a, Bf[pb][nt][0], Bf[pb][nt][1]);
                    }
                }
            }
        }
        if (c < 15) {
            STORE_B(so_nxt);
            asm volatile("cp.async.wait_group 0;");
        }
        __syncthreads();
    }

    // ---- epilogue ----
    const int rq = lane >> 2, q = lane & 3;
    if (G == 1) {
        float* s_sum = (float*)sm;
        float* s_sq = s_sum + 256;
        s_sum[t] = 0.f; s_sq[t] = 0.f;
        __syncthreads();
#pragma unroll
        for (int mt = 0; mt < MT; mt++) {
            int c_0 = ch0 + mt * 16 + rq, c_1 = c_0 + 8;
            float s0 = 0.f, q0 = 0.f, s1 = 0.f, q1 = 0.f;
#pragma unroll
            for (int nt = 0; nt < NT; nt++) {
                float v0 = d[mt][nt][0], v1 = d[mt][nt][1];
                float v2 = d[mt][nt][2], v3 = d[mt][nt][3];
                size_t PP = (size_t)P0 + pix0w + nt * 8 + q * 2;
                *(float2*)&g_h[(size_t)c_0 * NTOT + PP] = make_float2(v0, v1);
                *(float2*)&g_h[(size_t)c_1 * NTOT + PP] = make_float2(v2, v3);
                s0 += v0 + v1; q0 += v0 * v0 + v1 * v1;
                s1 += v2 + v3; q1 += v2 * v2 + v3 * v3;
            }
#pragma unroll
            for (int o = 1; o <= 2; o <<= 1) {
                s0 += __shfl_xor_sync(0xFFFFFFFFu, s0, o);
                q0 += __shfl_xor_sync(0xFFFFFFFFu, q0, o);
                s1 += __shfl_xor_sync(0xFFFFFFFFu, s1, o);
                q1 += __shfl_xor_sync(0xFFFFFFFFu, q1, o);
            }
            if (q == 0) {
                atomicAdd(&s_sum[c_0], s0); atomicAdd(&s_sq[c_0], q0);
                atomicAdd(&s_sum[c_1], s1); atomicAdd(&s_sq[c_1], q1);
            }
        }
        __syncthreads();
        atomicAdd(&g_sum[t], s_sum[t]);
        atomicAdd(&g_sumsq[t], s_sq[t]);
    } else {
        const size_t obase = (size_t)(P0 >> 14) * CHW + (P0 & 16383);
#pragma unroll
        for (int mt = 0; mt < MT; mt++) {
            int c_0 = ch0 + mt * 16 + rq, c_1 = c_0 + 8;
            float b0 = s_bias[c_0], b1 = s_bias[c_1];
#pragma unroll
            for (int nt = 0; nt < NT; nt++) {
                int pixL = pix0w + nt * 8 + q * 2;
                float f0 = s_fac[pixL], f1 = s_fac[pixL + 1];
                *(float2*)&out[obase + (size_t)c_0 * HW + pixL] =
                    make_float2((d[mt][nt][0] + b0) * f0, (d[mt][nt][1] + b0) * f1);
                *(float2*)&out[obase + (size_t)c_1 * HW + pixL] =
                    make_float2((d[mt][nt][2] + b1) * f0, (d[mt][nt][3] + b1) * f1);
            }
        }
    }
#undef ISSUE_A
#undef LOAD_B
#undef STORE_B
}

// ---------------- fused: BN finalize (per-block), BN+ReLU -> g_B2, GEMV, prob_x, u ----------------
__global__ void k_fuse(const float* __restrict__ gamma, const float* __restrict__ beta,
                       const float* __restrict__ Wm, const float* __restrict__ Ws,
                       const float* __restrict__ eps1, const float* __restrict__ eps50,
                       float* __restrict__ out) {
    __shared__ float s_a[Cc], s_b[Cc], s_wm[Cc], s_ws[Cc];
    int t = threadIdx.x;
    {
        float n = (float)NTOT;
        float mu = g_sum[t] / n;
        float var = fmaxf(g_sumsq[t] / n - mu * mu, 0.f);
        float a = gamma[t] * rsqrtf(var + 1e-5f);
        s_a[t] = a; s_b[t] = beta[t] - mu * a;
        s_wm[t] = Wm[t]; s_ws[t] = Ws[t];
    }
    __syncthreads();
    int P = blockIdx.x * 256 + t;
    int tile = P >> 7, px = P & 127;
    float m = 0.f, lv = 0.f;
#pragma unroll 4
    for (int cc = 0; cc < 16; cc++) {
#pragma unroll
        for (int kg = 0; kg < 2; kg++) {
            H8 u0;
#pragma unroll
            for (int e = 0; e < 8; e++) {
                int ch = cc * 16 + kg * 8 + e;
                float v = g_h[(size_t)ch * NTOT + P];
                float r = fmaxf(fmaf(s_a[ch], v, s_b[ch]), 0.f);
                m = fmaf(s_wm[ch], r, m);
                lv = fmaf(s_ws[ch], r, lv);
                u0.h[e] = __float2half_rn(r);
            }
            int u2 = (kg ^ (px >> 2)) & 1;
            *(uint4*)(g_B2 + (size_t)(tile * 16 + cc) * 2048 + px * 16 + u2 * 8) = u0.v;
        }
    }
    float stdv = __expf(0.5f * lv);
    out[PROB_OFF + P] = fmaf(eps1[P], stdv, m);
    int b = P >> 14, hw = P & (HW - 1);
    const float* e = eps50 + (size_t)b * NS * HW + hw;
    float s = 0.f, s2 = 0.f;
#pragma unroll
    for (int i = 0; i < NS; i++) {
        float tt = fmaf(e[(size_t)i * HW], stdv, m);
        float pv = __fdividef(1.f, 1.f + __expf(-tt));
        float qv = pv - 0.5f;
        s += qv; s2 = fmaf(qv, qv, s2);
    }
    g_u[P] = (s2 - s * s * (1.f / NS)) * (1.f / (NS - 1));
}

// ---------------- 3x 7x7 box filter, banded (64 blocks), + global min/max ----------------
#define BAND 16
#define HALO 9
#define LROWS (BAND + 2*HALO)   // 34
__global__ void k_box() {
    __shared__ float s0[LROWS][128], s1[LROWS][128];
    __shared__ unsigned int smn, smx;
    const int band = blockIdx.x, b = blockIdx.y;
    const int r0 = band * BAND - HALO;     // global row of ly=0
    const int tid = threadIdx.x;
    if (tid == 0) { smn = 0xFFFFFFFFu; smx = 0u; }
    const float* up = g_u + (size_t)b * HW;
    for (int i = tid; i < LROWS * 128; i += 256) {
        int ly = i >> 7, xx = i & 127;
        int gy = r0 + ly;
        s0[ly][xx] = (gy >= 0 && gy < 128) ? up[(gy << 7) + xx] : 0.f;
    }
    __syncthreads();
    int lo = 0, hi = LROWS;
    for (int it = 0; it < 3; it++) {
        for (int i = tid; i < LROWS * 128; i += 256) {
            int ly = i >> 7, xx = i & 127;
            if (ly >= lo && ly < hi) {
                int x0 = xx - 3 < 0 ? 0 : xx - 3;
                int x1 = xx + 3 > 127 ? 127 : xx + 3;
                float s = 0.f;
                for (int x2 = x0; x2 <= x1; x2++) s += s0[ly][x2];
                s1[ly][xx] = s;
            }
        }
        __syncthreads();
        lo += 3; hi -= 3;
        for (int i = tid; i < LROWS * 128; i += 256) {
            int ly = i >> 7, xx = i & 127;
            if (ly >= lo && ly < hi) {
                int gy = r0 + ly;
                float s = 0.f;
#pragma unroll
                for (int yy = -3; yy <= 3; yy++) s += s1[ly + yy][xx];
                s0[ly][xx] = (gy >= 0 && gy < 128) ? s : 0.f;   // per-iter zero pad
            }
        }
        __syncthreads();
    }
    float lmn = 3.4e38f, lmx = -3.4e38f;
    float* op = g_u2 + (size_t)b * HW + band * BAND * 128;
    for (int i = tid; i < BAND * 128; i += 256) {
        int ly = HALO + (i >> 7), xx = i & 127;
        float v = s0[ly][xx];
        op[i] = v;
        lmn = fminf(lmn, v); lmx = fmaxf(lmx, v);
    }
    atomicMin(&smn, __float_as_uint(lmn));
    atomicMax(&smx, __float_as_uint(lmx));
    __syncthreads();
    if (tid == 0) { atomicMin(&g_minb, smn); atomicMax(&g_maxb, smx); }
}

// ---------------- launch ----------------
extern "C" void kernel_launch(void* const* d_in, const int* in_sizes, int n_in,
                              void* d_out, int out_size) {
    const float* x     = (const float*)d_in[0];
    const float* Wproj = (const float*)d_in[1];
    const float* gamma = (const float*)d_in[2];
    const float* beta  = (const float*)d_in[3];
    const float* Wconv = (const float*)d_in[4];
    const float* bconv = (const float*)d_in[5];
    const float* Wmean = (const float*)d_in[6];
    const float* Wstd  = (const float*)d_in[7];
    const float* eps1  = (const float*)d_in[8];
    const float* eps50 = (const float*)d_in[9];
    const float* randu = (const float*)d_in[10];
    float* out = (float*)d_out;

    cudaFuncSetAttribute(k_gemm<1>, cudaFuncAttributeMaxDynamicSharedMemorySize, SMEM_G1);
    cudaFuncSetAttribute(k_gemm<2>, cudaFuncAttributeMaxDynamicSharedMemorySize, SMEM_G2);

    k_prep_w<<<512, 256>>>(Wproj, Wconv);
    k_gemm<1><<<NTOT / 64, 256, SMEM_G1>>>(x, nullptr, nullptr, nullptr);
    k_fuse<<<NTOT / 256, 256>>>(gamma, beta, Wmean, Wstd, eps1, eps50, out);
    k_box<<<dim3(Bb, Bb), 256>>>();
    k_gemm<2><<<NTOT / 64, 256, SMEM_G2>>>(nullptr, out, bconv, randu);
}

// round 15
// speedup vs baseline: 1.3682x; 1.0066x over previous
#include <cuda_runtime.h>
#include <cuda_fp16.h>
#include <math.h>
#include <stdint.h>

#define Cc 256
#define HW 16384
#define Bb 8
#define CHW (Cc*HW)
#define NTOT (Bb*HW)
#define TOTAL (Bb*CHW)
#define PROB_OFF TOTAL
#define NS 50

// G1: stage = A 16KB + B 2x2KB = 20KB. G2: stage = A 4KB + B 4KB = 8KB.
#define SMEM_G1 (2*20480 + 2048)
#define SMEM_G2 (2*8192  + 2048)

// ---------------- device globals ----------------
__device__ float g_h[TOTAL];                 // h pre-BN, [ch][P] fp32
__device__ __half g_B2[TOTAL];               // relu(bn(h)) fp16, pre-swizzled chunk tiles
__device__ __half g_wA[2*2*Cc*Cc];           // weights: [gemm][part][chunk][4096]
__device__ float g_sum[Cc], g_sumsq[Cc];
__device__ float g_u[NTOT], g_u2[NTOT];
__device__ unsigned int g_minb, g_maxb;

union H8 { __half h[8]; uint4 v; };
union H4 { __half h[4]; uint2 v; };

__device__ __forceinline__ uint32_t s2u(const void* p) {
    uint32_t a;
    asm("{ .reg .u64 t; cvta.to.shared.u64 t, %1; cvt.u32.u64 %0, t; }" : "=r"(a) : "l"(p));
    return a;
}
__device__ __forceinline__ void cpa16(uint32_t dst, const void* src) {
    asm volatile("cp.async.cg.shared.global [%0], [%1], 16;" :: "r"(dst), "l"(src));
}
__device__ __forceinline__ void ldmx4(uint32_t& a0, uint32_t& a1, uint32_t& a2, uint32_t& a3, uint32_t ad) {
    asm volatile("ldmatrix.sync.aligned.m8n8.x4.shared.b16 {%0,%1,%2,%3}, [%4];"
                 : "=r"(a0), "=r"(a1), "=r"(a2), "=r"(a3) : "r"(ad));
}
__device__ __forceinline__ void ldmx2(uint32_t& b0, uint32_t& b1, uint32_t ad) {
    asm volatile("ldmatrix.sync.aligned.m8n8.x2.shared.b16 {%0,%1}, [%2];"
                 : "=r"(b0), "=r"(b1) : "r"(ad));
}
__device__ __forceinline__ void mma16816(float* d, const uint32_t* a, uint32_t b0, uint32_t b1) {
    asm volatile("mma.sync.aligned.m16n8k16.row.col.f32.f16.f16.f32 "
                 "{%0,%1,%2,%3}, {%4,%5,%6,%7}, {%8,%9}, {%0,%1,%2,%3};"
                 : "+f"(d[0]), "+f"(d[1]), "+f"(d[2]), "+f"(d[3])
                 : "r"(a[0]), "r"(a[1]), "r"(a[2]), "r"(a[3]), "r"(b0), "r"(b1));
}

// ---------------- weight prep (+ per-call init), vectorized uint4 stores ----------------
__global__ void k_prep_w(const float* __restrict__ Wp, const float* __restrict__ Wc) {
    int t = threadIdx.x;
    if (blockIdx.x == 0) {
        g_sum[t] = 0.f; g_sumsq[t] = 0.f;
        if (t == 0) { g_minb = 0xFFFFFFFFu; g_maxb = 0u; }
    }
    int idx = blockIdx.x * 256 + t;            // 0..16383
    int half = idx & 1, kc = (idx >> 1) & 15, ch = (idx >> 5) & 255, g = idx >> 13;
    const float* W = (g ? Wc : Wp) + ch * Cc + kc * 16 + half * 8;
    H8 uH, uL;
#pragma unroll
    for (int e = 0; e < 8; e++) {
        float w = W[e];
        __half H = __float2half_rn(w);
        uH.h[e] = H;
        uL.h[e] = __float2half_rn(w - __half2float(H));
    }
    int unit = (half ^ (ch >> 2)) & 1;
    size_t base = (size_t)((g * 2) * 16 + kc) * 4096 + ch * 16 + unit * 8;
    *(uint4*)(g_wA + base)         = uH.v;
    *(uint4*)(g_wA + base + 65536) = uL.v;
}

// ---------------- mma.sync GEMM, K=256 in 16 chunks, 2-stage, occ>=2 ----------------
// G=1: N-SPLIT. tile 256ch x 64px per CTA. B = x fp32 (2-way fp16 split, 3 terms)
//      -> g_h + BN stats.
// G=2: M-SPLIT. tile 128ch x 128px per CTA pair. SINGLE TERM Ah*Bh, B = g_B2 via
//      cp.async -> out with bias + (1-u)*mask
template<int G>
__global__ __launch_bounds__(256, 2)
void k_gemm(const float* __restrict__ x, float* __restrict__ out,
            const float* __restrict__ bconv, const float* __restrict__ randu) {
    extern __shared__ __align__(16) char sm[];
    const uint32_t sb = s2u(sm);
    const int t = threadIdx.x, wid = t >> 5, lane = t & 31;

    constexpr int STGG = (G == 1) ? 20480 : 8192;   // stage bytes
    constexpr int MT   = (G == 1) ? 4 : 2;          // 16-ch M-tiles per warp
    constexpr int NT   = (G == 1) ? 4 : 8;          // 8-px N-tiles per warp
    constexpr int BOF  = (G == 1) ? 16384 : 4096;   // B offset in stage
    constexpr int BPS  = 2048;                      // G1 B part stride
    constexpr int FACO = 2 * STGG;

    const int tileIdx = (G == 1) ? blockIdx.x : (blockIdx.x >> 1);
    const int mhalf   = (G == 1) ? 0 : (blockIdx.x & 1);
    const int P0      = (G == 1) ? tileIdx * 64 : tileIdx * 128;

    const int ch0l  = (wid >> 1) * (MT * 16);
    const int ch0   = mhalf * 128 + ch0l;
    const int pix0w = (wid & 1) * (NT * 8);
    const int aRow = lane & 15, aUnit = lane >> 4;
    const int l15 = lane & 15;
    const int bRowOff = l15 & 7, bUnit = (l15 >> 3) & 1;
    const int px = t & 63, kseg = t >> 6;          // G1 B loader

    float* s_fac  = (float*)(sm + FACO);
    float* s_bias = (float*)(sm + FACO + 512);
    if (G == 2) {
        if (t < 128) {
            float mn = __uint_as_float(g_minb), mx = __uint_as_float(g_maxb);
            float un = (g_u2[P0 + t] - mn) / (mx - mn);
            s_fac[t] = (1.f - un) * ((un < randu[P0 + t]) ? 1.f : 0.f);
        }
        s_bias[t] = bconv[t];
    }

    float d[MT][NT][4];
#pragma unroll
    for (int i = 0; i < MT; i++)
#pragma unroll
        for (int j = 0; j < NT; j++)
#pragma unroll
            for (int e = 0; e < 4; e++) d[i][j][e] = 0.f;

    float bf[4];
    const float* xs = x + (size_t)(P0 >> 14) * CHW + (P0 & 16383) + px;

#define ISSUE_A(cc, so) do { \
    if (G == 1) { \
        _Pragma("unroll") \
        for (int i = 0; i < 4; i++) { \
            int u = t + i * 256; \
            int p = u >> 9, w = u & 511; \
            const char* src = (const char*)g_wA + (size_t)(p * 16 + (cc)) * 8192 + w * 16; \
            cpa16(sb + (so) + p * 8192 + w * 16, src); \
        } \
    } else { \
        const char* src = (const char*)g_wA + (size_t)(2 * 16 + (cc)) * 8192 + mhalf * 4096 + t * 16; \
        cpa16(sb + (so) + t * 16, src); \
        const char* srcb = (const char*)g_B2 + ((size_t)(tileIdx * 16 + (cc)) * 4096) + t * 16; \
        cpa16(sb + (so) + BOF + t * 16, srcb); \
    } \
    asm volatile("cp.async.commit_group;"); \
} while (0)

#define LOAD_B(cc) do { \
    if (G == 1) { \
        _Pragma("unroll") \
        for (int e = 0; e < 4; e++) bf[e] = xs[(size_t)((cc) * 16 + kseg * 4 + e) * HW]; \
    } \
} while (0)

#define STORE_B(so) do { \
    if (G == 1) { \
        H4 u0, u1; \
        _Pragma("unroll") \
        for (int e = 0; e < 4; e++) { \
            u0.h[e] = __float2half_rn(bf[e]); \
            u1.h[e] = __float2half_rn(bf[e] - __half2float(u0.h[e])); \
        } \
        int sunit = (kseg >> 1) ^ ((px >> 2) & 1); \
        char* dst = sm + (so) + BOF + px * 32 + sunit * 16 + (kseg & 1) * 8; \
        *(uint2*)(dst) = u0.v; \
        *(uint2*)(dst + BPS) = u1.v; \
    } \
} while (0)

    // prologue: chunk 0
    LOAD_B(0);
    ISSUE_A(0, 0);
    STORE_B(0);
    asm volatile("cp.async.wait_group 0;");
    __syncthreads();

    for (int c = 0; c < 16; c++) {
        const uint32_t so_cur = (c & 1) * STGG;
        const uint32_t so_nxt = ((c + 1) & 1) * STGG;
        if (c < 15) {
            ISSUE_A(c + 1, so_nxt);
            LOAD_B(c + 1);
        }
        // ---- MMA on current stage ----
        {
            uint32_t Ast = sb + so_cur;
            uint32_t Bst = Ast + BOF;
            constexpr int NPB = (G == 1) ? 2 : 1;
            constexpr int NPA = (G == 1) ? 2 : 1;
            uint32_t Bf[NPB][NT][2];
#pragma unroll
            for (int p = 0; p < NPB; p++)
#pragma unroll
                for (int nt = 0; nt < NT; nt++) {
                    int row = pix0w + nt * 8 + bRowOff;
                    uint32_t ad = Bst + p * BPS + row * 32 + (((bUnit ^ (row >> 2)) & 1) << 4);
                    ldmx2(Bf[p][nt][0], Bf[p][nt][1], ad);
                }
#pragma unroll
            for (int mt = 0; mt < MT; mt++) {
#pragma unroll
                for (int pa = 0; pa < NPA; pa++) {
                    int row = ch0l + mt * 16 + aRow;
                    uint32_t ad = Ast + pa * 8192 + row * 32 + (((aUnit ^ (row >> 2)) & 1) << 4);
                    uint32_t a[4];
                    ldmx4(a[0], a[1], a[2], a[3], ad);
                    const int nb = (G == 1) ? (2 - pa) : 1;   // G1: AhBh,AhBl,AlBh  G2: AhBh
#pragma unroll
                    for (int pb = 0; pb < NPB; pb++) {
                        if (pb >= nb) break;
#pragma unroll
                        for (int nt = 0; nt < NT; nt++)
                            mma16816(d[mt][nt], a, Bf[pb][nt][0], Bf[pb][nt][1]);
                    }
                }
            }
        }
        if (c < 15) {
            STORE_B(so_nxt);
            asm volatile("cp.async.wait_group 0;");
        }
        __syncthreads();
    }

    // ---- epilogue ----
    const int rq = lane >> 2, q = lane & 3;
    if (G == 1) {
        float* s_sum = (float*)sm;
        float* s_sq = s_sum + 256;
        s_sum[t] = 0.f; s_sq[t] = 0.f;
        __syncthreads();
#pragma unroll
        for (int mt = 0; mt < MT; mt++) {
            int c_0 = ch0 + mt * 16 + rq, c_1 = c_0 + 8;
            float s0 = 0.f, q0 = 0.f, s1 = 0.f, q1 = 0.f;
#pragma unroll
            for (int nt = 0; nt < NT; nt++) {
                float v0 = d[mt][nt][0], v1 = d[mt][nt][1];
                float v2 = d[mt][nt][2], v3 = d[mt][nt][3];
                size_t PP = (size_t)P0 + pix0w + nt * 8 + q * 2;
                *(float2*)&g_h[(size_t)c_0 * NTOT + PP] = make_float2(v0, v1);
                *(float2*)&g_h[(size_t)c_1 * NTOT + PP] = make_float2(v2, v3);
                s0 += v0 + v1; q0 += v0 * v0 + v1 * v1;
                s1 += v2 + v3; q1 += v2 * v2 + v3 * v3;
            }
#pragma unroll
            for (int o = 1; o <= 2; o <<= 1) {
                s0 += __shfl_xor_sync(0xFFFFFFFFu, s0, o);
                q0 += __shfl_xor_sync(0xFFFFFFFFu, q0, o);
                s1 += __shfl_xor_sync(0xFFFFFFFFu, s1, o);
                q1 += __shfl_xor_sync(0xFFFFFFFFu, q1, o);
            }
            if (q == 0) {
                atomicAdd(&s_sum[c_0], s0); atomicAdd(&s_sq[c_0], q0);
                atomicAdd(&s_sum[c_1], s1); atomicAdd(&s_sq[c_1], q1);
            }
        }
        __syncthreads();
        atomicAdd(&g_sum[t], s_sum[t]);
        atomicAdd(&g_sumsq[t], s_sq[t]);
    } else {
        const size_t obase = (size_t)(P0 >> 14) * CHW + (P0 & 16383);
#pragma unroll
        for (int mt = 0; mt < MT; mt++) {
            int c_0 = ch0 + mt * 16 + rq, c_1 = c_0 + 8;
            float b0 = s_bias[c_0], b1 = s_bias[c_1];
#pragma unroll
            for (int nt = 0; nt < NT; nt++) {
                int pixL = pix0w + nt * 8 + q * 2;
                float f0 = s_fac[pixL], f1 = s_fac[pixL + 1];
                *(float2*)&out[obase + (size_t)c_0 * HW + pixL] =
                    make_float2((d[mt][nt][0] + b0) * f0, (d[mt][nt][1] + b0) * f1);
                *(float2*)&out[obase + (size_t)c_1 * HW + pixL] =
                    make_float2((d[mt][nt][2] + b1) * f0, (d[mt][nt][3] + b1) * f1);
            }
        }
    }
#undef ISSUE_A
#undef LOAD_B
#undef STORE_B
}

// ---------------- fused: BN finalize + BN+ReLU -> g_B2 + GEMV + prob_x + u ----------------
// 512 threads: pixel P handled by thread pair (half=0: ch 0-127 & samples 0-24,
// half=1: ch 128-255 & samples 25-49), partials combined in smem.
__global__ __launch_bounds__(512)
void k_fuse(const float* __restrict__ gamma, const float* __restrict__ beta,
            const float* __restrict__ Wm, const float* __restrict__ Ws,
            const float* __restrict__ eps1, const float* __restrict__ eps50,
            float* __restrict__ out) {
    __shared__ float s_a[Cc], s_b[Cc], s_wm[Cc], s_ws[Cc];
    __shared__ float r0[2][256], r1[2][256];
    const int tt = threadIdx.x;
    const int t = tt & 255, half = tt >> 8;
    if (half == 0) {
        float n = (float)NTOT;
        float mu = g_sum[t] / n;
        float var = fmaxf(g_sumsq[t] / n - mu * mu, 0.f);
        float a = gamma[t] * rsqrtf(var + 1e-5f);
        s_a[t] = a; s_b[t] = beta[t] - mu * a;
        s_wm[t] = Wm[t]; s_ws[t] = Ws[t];
    }
    __syncthreads();
    const int P = blockIdx.x * 256 + t;
    const int tile = P >> 7, px = P & 127;
    float m = 0.f, lv = 0.f;
#pragma unroll 2
    for (int cc = half * 8; cc < half * 8 + 8; cc++) {
#pragma unroll
        for (int kg = 0; kg < 2; kg++) {
            H8 u0;
#pragma unroll
            for (int e = 0; e < 8; e++) {
                int ch = cc * 16 + kg * 8 + e;
                float v = g_h[(size_t)ch * NTOT + P];
                float r = fmaxf(fmaf(s_a[ch], v, s_b[ch]), 0.f);
                m = fmaf(s_wm[ch], r, m);
                lv = fmaf(s_ws[ch], r, lv);
                u0.h[e] = __float2half_rn(r);
            }
            int u2 = (kg ^ (px >> 2)) & 1;
            *(uint4*)(g_B2 + (size_t)(tile * 16 + cc) * 2048 + px * 16 + u2 * 8) = u0.v;
        }
    }
    r0[half][t] = m; r1[half][t] = lv;
    __syncthreads();
    m  = r0[0][t] + r0[1][t];
    lv = r1[0][t] + r1[1][t];
    float stdv = __expf(0.5f * lv);
    if (half == 0) out[PROB_OFF + P] = fmaf(eps1[P], stdv, m);
    const int b = P >> 14, hw = P & (HW - 1);
    const float* e = eps50 + (size_t)b * NS * HW + hw + (size_t)(half * 25) * HW;
    float s = 0.f, s2 = 0.f;
#pragma unroll
    for (int i = 0; i < 25; i++) {
        float tv = fmaf(e[(size_t)i * HW], stdv, m);
        float pv = __fdividef(1.f, 1.f + __expf(-tv));
        float qv = pv - 0.5f;
        s += qv; s2 = fmaf(qv, qv, s2);
    }
    __syncthreads();           // all reads of r0/r1 done before reuse
    r0[half][t] = s; r1[half][t] = s2;
    __syncthreads();
    if (half == 0) {
        float st = r0[0][t] + r0[1][t], s2t = r1[0][t] + r1[1][t];
        g_u[P] = (s2t - st * st * (1.f / NS)) * (1.f / (NS - 1));
    }
}

// ---------------- 3x 7x7 box filter, banded (128 blocks), + global min/max ----------------
#define BAND 8
#define HALO 9
#define LROWS (BAND + 2*HALO)   // 26
__global__ void k_box() {
    __shared__ float s0[LROWS][128], s1[LROWS][128];
    __shared__ unsigned int smn, smx;
    const int band = blockIdx.x, b = blockIdx.y;
    const int r0 = band * BAND - HALO;     // global row of ly=0
    const int tid = threadIdx.x;
    if (tid == 0) { smn = 0xFFFFFFFFu; smx = 0u; }
    const float* up = g_u + (size_t)b * HW;
    for (int i = tid; i < LROWS * 128; i += 256) {
        int ly = i >> 7, xx = i & 127;
        int gy = r0 + ly;
        s0[ly][xx] = (gy >= 0 && gy < 128) ? up[(gy << 7) + xx] : 0.f;
    }
    __syncthreads();
    int lo = 0, hi = LROWS;
    for (int it = 0; it < 3; it++) {
        for (int i = tid; i < LROWS * 128; i += 256) {
            int ly = i >> 7, xx = i & 127;
            if (ly >= lo && ly < hi) {
                int x0 = xx - 3 < 0 ? 0 : xx - 3;
                int x1 = xx + 3 > 127 ? 127 : xx + 3;
                float s = 0.f;
                for (int x2 = x0; x2 <= x1; x2++) s += s0[ly][x2];
                s1[ly][xx] = s;
            }
        }
        __syncthreads();
        lo += 3; hi -= 3;
        for (int i = tid; i < LROWS * 128; i += 256) {
            int ly = i >> 7, xx = i & 127;
            if (ly >= lo && ly < hi) {
                int gy = r0 + ly;
                float s = 0.f;
#pragma unroll
                for (int yy = -3; yy <= 3; yy++) s += s1[ly + yy][xx];
                s0[ly][xx] = (gy >= 0 && gy < 128) ? s : 0.f;   // per-iter zero pad
            }
        }
        __syncthreads();
    }
    float lmn = 3.4e38f, lmx = -3.4e38f;
    float* op = g_u2 + (size_t)b * HW + band * BAND * 128;
    for (int i = tid; i < BAND * 128; i += 256) {
        int ly = HALO + (i >> 7), xx = i & 127;
        float v = s0[ly][xx];
        op[i] = v;
        lmn = fminf(lmn, v); lmx = fmaxf(lmx, v);
    }
    atomicMin(&smn, __float_as_uint(lmn));
    atomicMax(&smx, __float_as_uint(lmx));
    __syncthreads();
    if (tid == 0) { atomicMin(&g_minb, smn); atomicMax(&g_maxb, smx); }
}

// ---------------- launch ----------------
extern "C" void kernel_launch(void* const* d_in, const int* in_sizes, int n_in,
                              void* d_out, int out_size) {
    const float* x     = (const float*)d_in[0];
    const float* Wproj = (const float*)d_in[1];
    const float* gamma = (const float*)d_in[2];
    const float* beta  = (const float*)d_in[3];
    const float* Wconv = (const float*)d_in[4];
    const float* bconv = (const float*)d_in[5];
    const float* Wmean = (const float*)d_in[6];
    const float* Wstd  = (const float*)d_in[7];
    const float* eps1  = (const float*)d_in[8];
    const float* eps50 = (const float*)d_in[9];
    const float* randu = (const float*)d_in[10];
    float* out = (float*)d_out;

    cudaFuncSetAttribute(k_gemm<1>, cudaFuncAttributeMaxDynamicSharedMemorySize, SMEM_G1);
    cudaFuncSetAttribute(k_gemm<2>, cudaFuncAttributeMaxDynamicSharedMemorySize, SMEM_G2);

    k_prep_w<<<64, 256>>>(Wproj, Wconv);
    k_gemm<1><<<NTOT / 64, 256, SMEM_G1>>>(x, nullptr, nullptr, nullptr);
    k_fuse<<<NTOT / 256, 512>>>(gamma, beta, Wmean, Wstd, eps1, eps50, out);
    k_box<<<dim3(128 / BAND, Bb), 256>>>();
    k_gemm<2><<<NTOT / 64, 256, SMEM_G2>>>(nullptr, out, bconv, randu);
}

// round 16
// speedup vs baseline: 1.5327x; 1.1203x over previous
#include <cuda_runtime.h>
#include <cuda_fp16.h>
#include <math.h>
#include <stdint.h>

#define Cc 256
#define HW 16384
#define Bb 8
#define CHW (Cc*HW)
#define NTOT (Bb*HW)
#define TOTAL (Bb*CHW)
#define PROB_OFF TOTAL
#define NS 50

// G1: 2 stages x 20KB. G2: 3 stages x 8KB.
#define SMEM_G1 (2*20480 + 2048)
#define SMEM_G2 (3*8192  + 2048)

// ---------------- device globals ----------------
__device__ float g_h[TOTAL];                 // h pre-BN, [ch][P] fp32
__device__ __half g_B2[TOTAL];               // relu(bn(h)) fp16, pre-swizzled chunk tiles
__device__ __half g_wA[2*2*Cc*Cc];           // weights: [gemm][part][chunk][4096]
__device__ float g_sum[Cc], g_sumsq[Cc];
__device__ float g_u[NTOT], g_u2[NTOT];
__device__ unsigned int g_minb, g_maxb;

union H8 { __half h[8]; uint4 v; };
union H4 { __half h[4]; uint2 v; };

__device__ __forceinline__ uint32_t s2u(const void* p) {
    uint32_t a;
    asm("{ .reg .u64 t; cvta.to.shared.u64 t, %1; cvt.u32.u64 %0, t; }" : "=r"(a) : "l"(p));
    return a;
}
__device__ __forceinline__ void cpa16(uint32_t dst, const void* src) {
    asm volatile("cp.async.cg.shared.global [%0], [%1], 16;" :: "r"(dst), "l"(src));
}
__device__ __forceinline__ void ldmx4(uint32_t& a0, uint32_t& a1, uint32_t& a2, uint32_t& a3, uint32_t ad) {
    asm volatile("ldmatrix.sync.aligned.m8n8.x4.shared.b16 {%0,%1,%2,%3}, [%4];"
                 : "=r"(a0), "=r"(a1), "=r"(a2), "=r"(a3) : "r"(ad));
}
__device__ __forceinline__ void ldmx2(uint32_t& b0, uint32_t& b1, uint32_t ad) {
    asm volatile("ldmatrix.sync.aligned.m8n8.x2.shared.b16 {%0,%1}, [%2];"
                 : "=r"(b0), "=r"(b1) : "r"(ad));
}
__device__ __forceinline__ void mma16816(float* d, const uint32_t* a, uint32_t b0, uint32_t b1) {
    asm volatile("mma.sync.aligned.m16n8k16.row.col.f32.f16.f16.f32 "
                 "{%0,%1,%2,%3}, {%4,%5,%6,%7}, {%8,%9}, {%0,%1,%2,%3};"
                 : "+f"(d[0]), "+f"(d[1]), "+f"(d[2]), "+f"(d[3])
                 : "r"(a[0]), "r"(a[1]), "r"(a[2]), "r"(a[3]), "r"(b0), "r"(b1));
}

// ---------------- weight prep (+ per-call init), vectorized uint4 stores ----------------
__global__ void k_prep_w(const float* __restrict__ Wp, const float* __restrict__ Wc) {
    int t = threadIdx.x;
    if (blockIdx.x == 0) {
        g_sum[t] = 0.f; g_sumsq[t] = 0.f;
        if (t == 0) { g_minb = 0xFFFFFFFFu; g_maxb = 0u; }
    }
    int idx = blockIdx.x * 256 + t;            // 0..16383
    int half = idx & 1, kc = (idx >> 1) & 15, ch = (idx >> 5) & 255, g = idx >> 13;
    const float* W = (g ? Wc : Wp) + ch * Cc + kc * 16 + half * 8;
    H8 uH, uL;
#pragma unroll
    for (int e = 0; e < 8; e++) {
        float w = W[e];
        __half H = __float2half_rn(w);
        uH.h[e] = H;
        uL.h[e] = __float2half_rn(w - __half2float(H));
    }
    int unit = (half ^ (ch >> 2)) & 1;
    size_t base = (size_t)((g * 2) * 16 + kc) * 4096 + ch * 16 + unit * 8;
    *(uint4*)(g_wA + base)         = uH.v;
    *(uint4*)(g_wA + base + 65536) = uL.v;
}

// ---------------- mma.sync GEMM, K=256 in 16 chunks ----------------
// G=1: N-SPLIT. 256ch x 64px per CTA, 2-stage (register B path). 3 terms -> g_h + BN stats.
// G=2: M-SPLIT. 128ch x 128px per CTA pair, 3-stage pure cp.async. 1 term Ah*Bh
//      -> out with bias + (1-u)*mask
template<int G>
__global__ __launch_bounds__(256, 2)
void k_gemm(const float* __restrict__ x, float* __restrict__ out,
            const float* __restrict__ bconv, const float* __restrict__ randu) {
    extern __shared__ __align__(16) char sm[];
    const uint32_t sb = s2u(sm);
    const int t = threadIdx.x, wid = t >> 5, lane = t & 31;

    constexpr int STGG = (G == 1) ? 20480 : 8192;   // stage bytes
    constexpr int NSTG = (G == 1) ? 2 : 3;
    constexpr int MT   = (G == 1) ? 4 : 2;          // 16-ch M-tiles per warp
    constexpr int NT   = (G == 1) ? 4 : 8;          // 8-px N-tiles per warp
    constexpr int BOF  = (G == 1) ? 16384 : 4096;   // B offset in stage
    constexpr int BPS  = 2048;                      // G1 B part stride
    constexpr int FACO = NSTG * STGG;

    const int tileIdx = (G == 1) ? blockIdx.x : (blockIdx.x >> 1);
    const int mhalf   = (G == 1) ? 0 : (blockIdx.x & 1);
    const int P0      = (G == 1) ? tileIdx * 64 : tileIdx * 128;

    const int ch0l  = (wid >> 1) * (MT * 16);
    const int ch0   = mhalf * 128 + ch0l;
    const int pix0w = (wid & 1) * (NT * 8);
    const int aRow = lane & 15, aUnit = lane >> 4;
    const int l15 = lane & 15;
    const int bRowOff = l15 & 7, bUnit = (l15 >> 3) & 1;
    const int px = t & 63, kseg = t >> 6;          // G1 B loader

    float* s_fac  = (float*)(sm + FACO);
    float* s_bias = (float*)(sm + FACO + 512);
    if (G == 2) {
        if (t < 128) {
            float mn = __uint_as_float(g_minb), mx = __uint_as_float(g_maxb);
            float un = (g_u2[P0 + t] - mn) / (mx - mn);
            s_fac[t] = (1.f - un) * ((un < randu[P0 + t]) ? 1.f : 0.f);
        }
        s_bias[t] = bconv[t];
    }

    float d[MT][NT][4];
#pragma unroll
    for (int i = 0; i < MT; i++)
#pragma unroll
        for (int j = 0; j < NT; j++)
#pragma unroll
            for (int e = 0; e < 4; e++) d[i][j][e] = 0.f;

    float bf[4];
    const float* xs = x + (size_t)(P0 >> 14) * CHW + (P0 & 16383) + px;

#define ISSUE_A(cc, so) do { \
    if (G == 1) { \
        _Pragma("unroll") \
        for (int i = 0; i < 4; i++) { \
            int u = t + i * 256; \
            int p = u >> 9, w = u & 511; \
            const char* src = (const char*)g_wA + (size_t)(p * 16 + (cc)) * 8192 + w * 16; \
            cpa16(sb + (so) + p * 8192 + w * 16, src); \
        } \
    } else { \
        const char* src = (const char*)g_wA + (size_t)(2 * 16 + (cc)) * 8192 + mhalf * 4096 + t * 16; \
        cpa16(sb + (so) + t * 16, src); \
        const char* srcb = (const char*)g_B2 + ((size_t)(tileIdx * 16 + (cc)) * 4096) + t * 16; \
        cpa16(sb + (so) + BOF + t * 16, srcb); \
    } \
    asm volatile("cp.async.commit_group;"); \
} while (0)

#define LOAD_B(cc) do { \
    if (G == 1) { \
        _Pragma("unroll") \
        for (int e = 0; e < 4; e++) bf[e] = xs[(size_t)((cc) * 16 + kseg * 4 + e) * HW]; \
    } \
} while (0)

#define STORE_B(so) do { \
    if (G == 1) { \
        H4 u0, u1; \
        _Pragma("unroll") \
        for (int e = 0; e < 4; e++) { \
            u0.h[e] = __float2half_rn(bf[e]); \
            u1.h[e] = __float2half_rn(bf[e] - __half2float(u0.h[e])); \
        } \
        int sunit = (kseg >> 1) ^ ((px >> 2) & 1); \
        char* dst = sm + (so) + BOF + px * 32 + sunit * 16 + (kseg & 1) * 8; \
        *(uint2*)(dst) = u0.v; \
        *(uint2*)(dst + BPS) = u1.v; \
    } \
} while (0)

    // prologue
    if (G == 1) {
        LOAD_B(0);
        ISSUE_A(0, 0);
        STORE_B(0);
        asm volatile("cp.async.wait_group 0;");
    } else {
        ISSUE_A(0, 0);
        ISSUE_A(1, STGG);
        asm volatile("cp.async.wait_group 1;");
    }
    __syncthreads();

    for (int c = 0; c < 16; c++) {
        const uint32_t so_cur = (c % NSTG) * STGG;
        if (G == 1) {
            const uint32_t so_nxt = ((c + 1) % NSTG) * STGG;
            if (c < 15) {
                ISSUE_A(c + 1, so_nxt);
                LOAD_B(c + 1);
            }
        } else {
            if (c + 2 < 16) ISSUE_A(c + 2, ((c + 2) % NSTG) * STGG);
        }
        // ---- MMA on current stage ----
        {
            uint32_t Ast = sb + so_cur;
            uint32_t Bst = Ast + BOF;
            constexpr int NPB = (G == 1) ? 2 : 1;
            constexpr int NPA = (G == 1) ? 2 : 1;
            uint32_t Bf[NPB][NT][2];
#pragma unroll
            for (int p = 0; p < NPB; p++)
#pragma unroll
                for (int nt = 0; nt < NT; nt++) {
                    int row = pix0w + nt * 8 + bRowOff;
                    uint32_t ad = Bst + p * BPS + row * 32 + (((bUnit ^ (row >> 2)) & 1) << 4);
                    ldmx2(Bf[p][nt][0], Bf[p][nt][1], ad);
                }
#pragma unroll
            for (int mt = 0; mt < MT; mt++) {
#pragma unroll
                for (int pa = 0; pa < NPA; pa++) {
                    int row = ch0l + mt * 16 + aRow;
                    uint32_t ad = Ast + pa * 8192 + row * 32 + (((aUnit ^ (row >> 2)) & 1) << 4);
                    uint32_t a[4];
                    ldmx4(a[0], a[1], a[2], a[3], ad);
                    const int nb = (G == 1) ? (2 - pa) : 1;   // G1: AhBh,AhBl,AlBh  G2: AhBh
#pragma unroll
                    for (int pb = 0; pb < NPB; pb++) {
                        if (pb >= nb) break;
#pragma unroll
                        for (int nt = 0; nt < NT; nt++)
                            mma16816(d[mt][nt], a, Bf[pb][nt][0], Bf[pb][nt][1]);
                    }
                }
            }
        }
        if (G == 1) {
            if (c < 15) {
                STORE_B(((c + 1) % NSTG) * STGG);
                asm volatile("cp.async.wait_group 0;");
            }
        } else {
            if (c + 2 < 16)      asm volatile("cp.async.wait_group 1;");
            else if (c + 1 < 16) asm volatile("cp.async.wait_group 0;");
        }
        __syncthreads();
    }

    // ---- epilogue ----
    const int rq = lane >> 2, q = lane & 3;
    if (G == 1) {
        float* s_sum = (float*)sm;
        float* s_sq = s_sum + 256;
        s_sum[t] = 0.f; s_sq[t] = 0.f;
        __syncthreads();
#pragma unroll
        for (int mt = 0; mt < MT; mt++) {
            int c_0 = ch0 + mt * 16 + rq, c_1 = c_0 + 8;
            float s0 = 0.f, q0 = 0.f, s1 = 0.f, q1 = 0.f;
#pragma unroll
            for (int nt = 0; nt < NT; nt++) {
                float v0 = d[mt][nt][0], v1 = d[mt][nt][1];
                float v2 = d[mt][nt][2], v3 = d[mt][nt][3];
                size_t PP = (size_t)P0 + pix0w + nt * 8 + q * 2;
                *(float2*)&g_h[(size_t)c_0 * NTOT + PP] = make_float2(v0, v1);
                *(float2*)&g_h[(size_t)c_1 * NTOT + PP] = make_float2(v2, v3);
                s0 += v0 + v1; q0 += v0 * v0 + v1 * v1;
                s1 += v2 + v3; q1 += v2 * v2 + v3 * v3;
            }
#pragma unroll
            for (int o = 1; o <= 2; o <<= 1) {
                s0 += __shfl_xor_sync(0xFFFFFFFFu, s0, o);
                q0 += __shfl_xor_sync(0xFFFFFFFFu, q0, o);
                s1 += __shfl_xor_sync(0xFFFFFFFFu, s1, o);
                q1 += __shfl_xor_sync(0xFFFFFFFFu, q1, o);
            }
            if (q == 0) {
                atomicAdd(&s_sum[c_0], s0); atomicAdd(&s_sq[c_0], q0);
                atomicAdd(&s_sum[c_1], s1); atomicAdd(&s_sq[c_1], q1);
            }
        }
        __syncthreads();
        atomicAdd(&g_sum[t], s_sum[t]);
        atomicAdd(&g_sumsq[t], s_sq[t]);
    } else {
        const size_t obase = (size_t)(P0 >> 14) * CHW + (P0 & 16383);
#pragma unroll
        for (int mt = 0; mt < MT; mt++) {
            int c_0 = ch0 + mt * 16 + rq, c_1 = c_0 + 8;
            float b0 = s_bias[c_0], b1 = s_bias[c_1];
#pragma unroll
            for (int nt = 0; nt < NT; nt++) {
                int pixL = pix0w + nt * 8 + q * 2;
                float f0 = s_fac[pixL], f1 = s_fac[pixL + 1];
                *(float2*)&out[obase + (size_t)c_0 * HW + pixL] =
                    make_float2((d[mt][nt][0] + b0) * f0, (d[mt][nt][1] + b0) * f1);
                *(float2*)&out[obase + (size_t)c_1 * HW + pixL] =
                    make_float2((d[mt][nt][2] + b1) * f0, (d[mt][nt][3] + b1) * f1);
            }
        }
    }
#undef ISSUE_A
#undef LOAD_B
#undef STORE_B
}

// ---------------- fused: BN finalize + BN+ReLU -> g_B2 + GEMV + prob_x + u ----------------
__global__ __launch_bounds__(512)
void k_fuse(const float* __restrict__ gamma, const float* __restrict__ beta,
            const float* __restrict__ Wm, const float* __restrict__ Ws,
            const float* __restrict__ eps1, const float* __restrict__ eps50,
            float* __restrict__ out) {
    __shared__ float s_a[Cc], s_b[Cc], s_wm[Cc], s_ws[Cc];
    __shared__ float r0[2][256], r1[2][256];
    const int tt = threadIdx.x;
    const int t = tt & 255, half = tt >> 8;
    if (half == 0) {
        float n = (float)NTOT;
        float mu = g_sum[t] / n;
        float var = fmaxf(g_sumsq[t] / n - mu * mu, 0.f);
        float a = gamma[t] * rsqrtf(var + 1e-5f);
        s_a[t] = a; s_b[t] = beta[t] - mu * a;
        s_wm[t] = Wm[t]; s_ws[t] = Ws[t];
    }
    __syncthreads();
    const int P = blockIdx.x * 256 + t;
    const int tile = P >> 7, px = P & 127;
    float m = 0.f, lv = 0.f;
#pragma unroll 2
    for (int cc = half * 8; cc < half * 8 + 8; cc++) {
#pragma unroll
        for (int kg = 0; kg < 2; kg++) {
            H8 u0;
#pragma unroll
            for (int e = 0; e < 8; e++) {
                int ch = cc * 16 + kg * 8 + e;
                float v = g_h[(size_t)ch * NTOT + P];
                float r = fmaxf(fmaf(s_a[ch], v, s_b[ch]), 0.f);
                m = fmaf(s_wm[ch], r, m);
                lv = fmaf(s_ws[ch], r, lv);
                u0.h[e] = __float2half_rn(r);
            }
            int u2 = (kg ^ (px >> 2)) & 1;
            *(uint4*)(g_B2 + (size_t)(tile * 16 + cc) * 2048 + px * 16 + u2 * 8) = u0.v;
        }
    }
    r0[half][t] = m; r1[half][t] = lv;
    __syncthreads();
    m  = r0[0][t] + r0[1][t];
    lv = r1[0][t] + r1[1][t];
    float stdv = __expf(0.5f * lv);
    if (half == 0) out[PROB_OFF + P] = fmaf(eps1[P], stdv, m);
    const int b = P >> 14, hw = P & (HW - 1);
    const float* e = eps50 + (size_t)b * NS * HW + hw + (size_t)(half * 25) * HW;
    float s = 0.f, s2 = 0.f;
#pragma unroll
    for (int i = 0; i < 25; i++) {
        float tv = fmaf(e[(size_t)i * HW], stdv, m);
        float pv = __fdividef(1.f, 1.f + __expf(-tv));
        float qv = pv - 0.5f;
        s += qv; s2 = fmaf(qv, qv, s2);
    }
    __syncthreads();
    r0[half][t] = s; r1[half][t] = s2;
    __syncthreads();
    if (half == 0) {
        float st = r0[0][t] + r0[1][t], s2t = r1[0][t] + r1[1][t];
        g_u[P] = (s2t - st * st * (1.f / NS)) * (1.f / (NS - 1));
    }
}

// ---------------- 3x 7x7 box filter, banded (128 blocks x 512 thr), + min/max ----------------
#define BAND 8
#define HALO 9
#define LROWS (BAND + 2*HALO)   // 26
__global__ __launch_bounds__(512)
void k_box() {
    __shared__ float s0[LROWS][128], s1[LROWS][128];
    __shared__ unsigned int smn, smx;
    const int band = blockIdx.x, b = blockIdx.y;
    const int r0 = band * BAND - HALO;     // global row of ly=0
    const int tid = threadIdx.x;
    if (tid == 0) { smn = 0xFFFFFFFFu; smx = 0u; }
    const float* up = g_u + (size_t)b * HW;
    for (int i = tid; i < LROWS * 128; i += 512) {
        int ly = i >> 7, xx = i & 127;
        int gy = r0 + ly;
        s0[ly][xx] = (gy >= 0 && gy < 128) ? up[(gy << 7) + xx] : 0.f;
    }
    __syncthreads();
    int lo = 0, hi = LROWS;
    for (int it = 0; it < 3; it++) {
        for (int i = tid; i < LROWS * 128; i += 512) {
            int ly = i >> 7, xx = i & 127;
            if (ly >= lo && ly < hi) {
                int x0 = xx - 3 < 0 ? 0 : xx - 3;
                int x1 = xx + 3 > 127 ? 127 : xx + 3;
                float s = 0.f;
                for (int x2 = x0; x2 <= x1; x2++) s += s0[ly][x2];
                s1[ly][xx] = s;
            }
        }
        __syncthreads();
        lo += 3; hi -= 3;
        for (int i = tid; i < LROWS * 128; i += 512) {
            int ly = i >> 7, xx = i & 127;
            if (ly >= lo && ly < hi) {
                int gy = r0 + ly;
                float s = 0.f;
#pragma unroll
                for (int yy = -3; yy <= 3; yy++) s += s1[ly + yy][xx];
                s0[ly][xx] = (gy >= 0 && gy < 128) ? s : 0.f;   // per-iter zero pad
            }
        }
        __syncthreads();
    }
    float lmn = 3.4e38f, lmx = -3.4e38f;
    float* op = g_u2 + (size_t)b * HW + band * BAND * 128;
    for (int i = tid; i < BAND * 128; i += 512) {
        int ly = HALO + (i >> 7), xx = i & 127;
        float v = s0[ly][xx];
        op[i] = v;
        lmn = fminf(lmn, v); lmx = fmaxf(lmx, v);
    }
    atomicMin(&smn, __float_as_uint(lmn));
    atomicMax(&smx, __float_as_uint(lmx));
    __syncthreads();
    if (tid == 0) { atomicMin(&g_minb, smn); atomicMax(&g_maxb, smx); }
}

// ---------------- launch ----------------
extern "C" void kernel_launch(void* const* d_in, const int* in_sizes, int n_in,
                              void* d_out, int out_size) {
    const float* x     = (const float*)d_in[0];
    const float* Wproj = (const float*)d_in[1];
    const float* gamma = (const float*)d_in[2];
    const float* beta  = (const float*)d_in[3];
    const float* Wconv = (const float*)d_in[4];
    const float* bconv = (const float*)d_in[5];
    const float* Wmean = (const float*)d_in[6];
    const float* Wstd  = (const float*)d_in[7];
    const float* eps1  = (const float*)d_in[8];
    const float* eps50 = (const float*)d_in[9];
    const float* randu = (const float*)d_in[10];
    float* out = (float*)d_out;

    cudaFuncSetAttribute(k_gemm<1>, cudaFuncAttributeMaxDynamicSharedMemorySize, SMEM_G1);
    cudaFuncSetAttribute(k_gemm<2>, cudaFuncAttributeMaxDynamicSharedMemorySize, SMEM_G2);

    k_prep_w<<<64, 256>>>(Wproj, Wconv);
    k_gemm<1><<<NTOT / 64, 256, SMEM_G1>>>(x, nullptr, nullptr, nullptr);
    k_fuse<<<NTOT / 256, 512>>>(gamma, beta, Wmean, Wstd, eps1, eps50, out);
    k_box<<<dim3(128 / BAND, Bb), 512>>>();
    k_gemm<2><<<NTOT / 64, 256, SMEM_G2>>>(nullptr, out, bconv, randu);
}